// round 7
// baseline (speedup 1.0000x reference)
#include <cuda_runtime.h>
#include <math.h>
#include <stdint.h>

// ---- problem constants ----
#define NG   208      // total gates: pop(8) + pushop(8) + pushfn(128) + calc(64)
#define VDIM 512
#define BB   256
#define SS   128
#define ZO   1e-6f
#define EPS  1e-8f

// ---- device scratch (no allocations allowed; __device__ globals are the
// sanctioned mechanism) ----
__device__ float d_M[32 * 32];                    // Gram of 32-dim basis
__device__ float d_Gn1[NG * 32];                  // basis . w_vec1 / max(||w_vec1||,eps)
__device__ float d_Gn2[NG * 32];                  // basis . w_vec2 / max(||w_vec2||,eps)
__device__ float d_NWv[NG * 3];                   // sigmoid(nw_raw)
__device__ float d_W0T[VDIM * NG];                // w_vec0 normalized, transposed [v][c]
__device__ float d_invnx[BB * SS];                // 1/max(||x_row||,eps)
__device__ float d_E0[(size_t)SS * BB * NG];      // precomputed vec0 interp term
__device__ float d_OC[(size_t)BB * SS * 32];      // output coefficients

// ============================================================
// Gram matrix of the 32-dim basis: b0 = ones, b1 = siv, b2+h = syms[h]
// grid (32,32), 32 threads (one warp) per block
// ============================================================
__global__ void k_gram(const float* __restrict__ siv, const float* __restrict__ syms) {
    int i = blockIdx.x, j = blockIdx.y;
    int lane = threadIdx.x;
    float s = 0.f;
    for (int v = lane; v < VDIM; v += 32) {
        float bi = (i == 0) ? 1.f : ((i == 1) ? siv[v] : syms[(i - 2) * VDIM + v]);
        float bj = (j == 0) ? 1.f : ((j == 1) ? siv[v] : syms[(j - 2) * VDIM + v]);
        s += bi * bj;
    }
    for (int o = 16; o; o >>= 1) s += __shfl_down_sync(0xffffffffu, s, o);
    if (lane == 0) d_M[i * 32 + j] = s;
}

// ============================================================
// Per-gate preprocessing: G matrices, norms, sigmoid(nw), normalized W0^T
// grid = 208 blocks (one per gate), 256 threads
// ============================================================
__global__ void k_setup(const float* __restrict__ siv, const float* __restrict__ syms,
                        const float* __restrict__ pop_w, const float* __restrict__ pop_nw,
                        const float* __restrict__ pushop_w, const float* __restrict__ pushop_nw,
                        const float* __restrict__ pushfn_w, const float* __restrict__ pushfn_nw,
                        const float* __restrict__ calc_w, const float* __restrict__ calc_nw) {
    int c = blockIdx.x;
    const float* wb;
    const float* nb;
    if (c < 8)        { wb = pop_w    + (size_t)c * 3 * VDIM;          nb = pop_nw    + (size_t)c * 3; }
    else if (c < 16)  { wb = pushop_w + (size_t)(c - 8) * 3 * VDIM;    nb = pushop_nw + (size_t)(c - 8) * 3; }
    else if (c < 144) { wb = pushfn_w + (size_t)(c - 16) * 3 * VDIM;   nb = pushfn_nw + (size_t)(c - 16) * 3; }
    else              { wb = calc_w   + (size_t)(c - 144) * 3 * VDIM;  nb = calc_nw   + (size_t)(c - 144) * 3; }

    __shared__ float sg[67];  // 64 basis dots (bi x {vec1,vec2}) + 3 squared norms
    int warp = threadIdx.x >> 5, lane = threadIdx.x & 31;
    for (int job = warp; job < 67; job += 8) {
        const float* w;
        int bi;
        if (job < 64) { bi = job >> 1; w = wb + ((job & 1) + 1) * VDIM; }
        else          { bi = -1;       w = wb + (job - 64) * VDIM; }
        float s = 0.f;
        for (int v = lane; v < VDIM; v += 32) {
            float wv = w[v];
            float bv = (bi < 0) ? wv
                     : ((bi == 0) ? 1.f : ((bi == 1) ? siv[v] : syms[(bi - 2) * VDIM + v]));
            s += wv * bv;
        }
        for (int o = 16; o; o >>= 1) s += __shfl_down_sync(0xffffffffu, s, o);
        if (!lane) sg[job] = s;
    }
    __syncthreads();
    if (threadIdx.x < 64) {
        int bi = threadIdx.x >> 1, vecsel = threadIdx.x & 1;
        float n = fmaxf(sqrtf(sg[65 + vecsel]), EPS);
        float g = sg[threadIdx.x] / n;
        if (vecsel == 0) d_Gn1[c * 32 + bi] = g;
        else             d_Gn2[c * 32 + bi] = g;
    }
    if (threadIdx.x < 3) d_NWv[c * 3 + threadIdx.x] = 1.f / (1.f + expf(-nb[threadIdx.x]));
    float n0 = fmaxf(sqrtf(sg[64]), EPS);
    for (int v = threadIdx.x; v < VDIM; v += blockDim.x)
        d_W0T[(size_t)v * NG + c] = wb[v] / n0;
}

// ============================================================
// Row norms of x: one warp per row
// ============================================================
__global__ void k_xnorm(const float* __restrict__ x) {
    int wg = (blockIdx.x * blockDim.x + threadIdx.x) >> 5;
    int lane = threadIdx.x & 31;
    int nwarps = (gridDim.x * blockDim.x) >> 5;
    for (int r = wg; r < BB * SS; r += nwarps) {
        const float* xr = x + (size_t)r * VDIM;
        float s = 0.f;
        for (int v = lane; v < VDIM; v += 32) { float t = xr[v]; s += t * t; }
        for (int o = 16; o; o >>= 1) s += __shfl_down_sync(0xffffffffu, s, o);
        if (!lane) d_invnx[r] = 1.f / fmaxf(sqrtf(s), EPS);
    }
}

// ============================================================
// E0 GEMM: E0[m][c] = nw0*|cos0| + (1-nw0)*(1-|cos0|)
// where m = s*256 + b, cos0 = (x_row . w0_c) * invnx (w-norm folded into W0T)
// grid = 512 blocks (64 rows each), 256 threads
// ============================================================
__global__ __launch_bounds__(256) void k_e0(const float* __restrict__ x) {
    __shared__ float xs[64][33];
    __shared__ float ws[32][224];
    __shared__ float snw[NG];
    int tid = threadIdx.x;
    int m0 = blockIdx.x * 64;
    if (tid < NG) snw[tid] = d_NWv[tid * 3];
    // zero the pad columns of ws once (cols 208..223 for all 32 k-rows)
#pragma unroll
    for (int e = 0; e < 2; e++) {
        int idx = tid + e * 256;
        if (idx < 512) { int kk = idx >> 4, cc = 208 + (idx & 15); ws[kk][cc] = 0.f; }
    }
    float acc[8][7];
#pragma unroll
    for (int u = 0; u < 8; u++)
#pragma unroll
        for (int cu = 0; cu < 7; cu++) acc[u][cu] = 0.f;
    int tr = tid >> 5, tc = tid & 31;

    for (int k0 = 0; k0 < VDIM; k0 += 32) {
        __syncthreads();
#pragma unroll
        for (int e = 0; e < 8; e++) {
            int idx = tid + e * 256;
            int r = idx >> 5, kk = idx & 31;
            int m = m0 + r;
            int b = m & 255, s = m >> 8;
            xs[r][kk] = x[((size_t)(b * SS + s)) * VDIM + k0 + kk];
        }
#pragma unroll
        for (int e = 0; e < 26; e++) {
            int idx = tid + e * 256;
            int kk = idx / 208, c = idx % 208;
            ws[kk][c] = d_W0T[(size_t)(k0 + kk) * NG + c];
        }
        __syncthreads();
#pragma unroll 8
        for (int kk = 0; kk < 32; kk++) {
            float xr[8];
#pragma unroll
            for (int u = 0; u < 8; u++) xr[u] = xs[tr * 8 + u][kk];
#pragma unroll
            for (int cu = 0; cu < 7; cu++) {
                float wv = ws[kk][tc + cu * 32];
#pragma unroll
                for (int u = 0; u < 8; u++) acc[u][cu] = fmaf(xr[u], wv, acc[u][cu]);
            }
        }
    }
    __syncthreads();
#pragma unroll
    for (int u = 0; u < 8; u++) {
        int m = m0 + tr * 8 + u;
        int b = m & 255, s = m >> 8;
        float inx = d_invnx[b * SS + s];
#pragma unroll
        for (int cu = 0; cu < 7; cu++) {
            int c = tc + cu * 32;
            if (c < NG) {
                float c0 = fabsf(acc[u][cu] * inx);
                float nw = snw[c];
                d_E0[(size_t)m * NG + c] = nw * c0 + (1.f - nw) * (1.f - c0);
            }
        }
    }
}

// ============================================================
// Sequential scan in 32-dim coefficient space.
// One block per batch lane, 256 threads, 128 steps, no cross-block deps.
// ============================================================
__global__ __launch_bounds__(256, 2) void k_scan(const float* __restrict__ sharp_in) {
    const int b = blockIdx.x;
    const int tid = threadIdx.x;
    __shared__ float sM[32][32];
    __shared__ float sA[2][4][32];    // stack coefficients
    __shared__ float sP[2][4];        // pointers
    __shared__ float sPk[2][32];      // peek coefficients
    __shared__ float sNp[2];          // peek norms
    __shared__ float sG[NG];          // gate activations
    __shared__ float sCoef[2][32];    // reduced push / out coefficients
    __shared__ float sPv[2][32];      // push value coefficients
    __shared__ float sProb[2][2];     // [k][0]=P(pop), [k][1]=P(push)

    float rG1[32], rG2[32];
    float nw1 = 0.f, nw2 = 0.f;
    if (tid < NG) {
#pragma unroll
        for (int i = 0; i < 32; i++) {
            rG1[i] = d_Gn1[tid * 32 + i];
            rG2[i] = d_Gn2[tid * 32 + i];
        }
        nw1 = d_NWv[tid * 3 + 1];
        nw2 = d_NWv[tid * 3 + 2];
    }
    for (int idx = tid; idx < 1024; idx += 256) sM[idx >> 5][idx & 31] = d_M[idx];
    {
        int k = tid >> 7, d = (tid >> 5) & 3, i = tid & 31;
        // init: all slots ZERO_OFFSET*ones, then hard-push init vec -> slot 1, ptr slot 1
        sA[k][d][i] = (d == 1) ? ((i == 1) ? 1.f : 0.f) : ((i == 0) ? ZO : 0.f);
        if (tid < 8) sP[tid >> 2][tid & 3] = ((tid & 3) == 1) ? 1.f : 0.f;
    }
    const float sh0 = sharp_in[0], sh1 = sharp_in[1];
    __syncthreads();

#define PEEK() do { \
    if (tid < 64) { int k_ = tid >> 5, i_ = tid & 31; float s_ = 0.f; \
        for (int d_ = 0; d_ < 4; d_++) s_ += sP[k_][d_] * sA[k_][d_][i_]; \
        sPk[k_][i_] = s_; } \
    __syncthreads(); \
    if (tid < 64) { int k_ = tid >> 5, i_ = tid & 31; \
        float pk_ = sPk[k_][i_]; float s_ = 0.f; \
        for (int j_ = 0; j_ < 32; j_++) s_ += sM[i_][j_] * sPk[k_][j_]; \
        float part_ = pk_ * s_; \
        for (int o_ = 16; o_; o_ >>= 1) part_ += __shfl_down_sync(0xffffffffu, part_, o_); \
        if (i_ == 0) sNp[k_] = sqrtf(fmaxf(part_, 0.f)); } \
    __syncthreads(); } while (0)

    PEEK();

    float e0c = (tid < NG) ? d_E0[((size_t)0 * BB + b) * NG + tid] : 0.f;

    for (int t = 0; t < SS; t++) {
        float e0n = 0.f;
        if (tid < NG && t < SS - 1) e0n = d_E0[((size_t)(t + 1) * BB + b) * NG + tid];

        // ---- phase A gates (pop / pushop / pushfn) with old peeks ----
        if (tid < 144) {
            float inv0 = 1.f / fmaxf(sNp[0], EPS);
            float inv1 = 1.f / fmaxf(sNp[1], EPS);
            float d1 = 0.f, d2 = 0.f;
#pragma unroll
            for (int i = 0; i < 32; i++) { d1 += sPk[0][i] * rG1[i]; d2 += sPk[1][i] * rG2[i]; }
            float c1 = fabsf(d1) * inv0;
            float c2 = fabsf(d2) * inv1;
            float t1 = nw1 * c1 + (1.f - nw1) * (1.f - c1);
            float t2 = nw2 * c2 + (1.f - nw2) * (1.f - c2);
            sG[tid] = e0c * t1 * t2;
        }
        __syncthreads();

        // push coefficients (sum over R=2) and pop/push probabilities
        if (tid < 64) {
            int k = tid >> 5, cc = tid & 31;
            int base = 16 + (k << 6) + (cc << 1);
            sCoef[k][cc] = sG[base] + sG[base + 1];
        }
        if (tid >= 64 && tid < 66) {
            int k = tid - 64;
            float sh = k ? sh1 : sh0;
            float pp = fmaxf(sG[k * 4 + 0], sG[k * 4 + 1]) * sh;
            float pn = fmaxf(sG[k * 4 + 2], sG[k * 4 + 3]) * sh;
            float m = fmaxf(pp, pn);
            float ea = expf(pp - m), eb = expf(pn - m);
            sProb[k][0] = ea / (ea + eb);
            float qp = fmaxf(sG[8 + k * 4 + 0], sG[8 + k * 4 + 1]) * sh;
            float qn = fmaxf(sG[8 + k * 4 + 2], sG[8 + k * 4 + 3]) * sh;
            float m2 = fmaxf(qp, qn);
            float ec = expf(qp - m2), ed = expf(qn - m2);
            sProb[k][1] = ec / (ec + ed);
        }
        __syncthreads();

        // push value coefficients: syms part + old peeks
        if (tid < 64) {
            int k = tid >> 5, i = tid & 31;
            float v = sCoef[k][30] * sPk[0][i] + sCoef[k][31] * sPk[1][i];
            if (i >= 2) v += sCoef[k][i - 2];
            sPv[k][i] = v;
        }
        __syncthreads();

        // ---- stack update: pop_or_nop then push_or_nop, all in coef space ----
        {
            int k = tid >> 7, d = (tid >> 5) & 3, i = tid & 31;
            float a   = sA[k][d][i];
            float pd  = sP[k][d];
            float pdp = sP[k][(d + 1) & 3];
            float pdm = sP[k][(d - 1) & 3];
            float pop  = sProb[k][0];
            float push = sProb[k][1];
            float pv = sPv[k][i];
            float ps = a * (1.f - pd) + ((i == 0) ? ZO : 0.f) * pd;
            float s1 = ps * pop + a * (1.f - pop);
            float prold = pd * pop + pdm * (1.f - pop);          // roll(p1,+1)[d]
            float p1d   = pdp * pop + pd * (1.f - pop);          // p1[d]
            float ps2 = s1 * (1.f - prold) + pv * prold;
            float s2 = ps2 * push + s1 * (1.f - push);
            float p2 = prold * push + p1d * (1.f - push);
            __syncthreads();
            sA[k][d][i] = s2;
            if (i == 0) sP[k][d] = p2;
        }
        __syncthreads();

        // ---- new peeks (also next step's old peeks) ----
        PEEK();

        // ---- phase B: calc gates with new peeks ----
        if (tid >= 144 && tid < NG) {
            float d1 = 0.f, d2 = 0.f;
#pragma unroll
            for (int i = 0; i < 32; i++) { d1 += sPk[0][i] * rG1[i]; d2 += sPk[1][i] * rG2[i]; }
            float c1 = fabsf(d1) / fmaxf(sNp[0], EPS);
            float c2 = fabsf(d2) / fmaxf(sNp[1], EPS);
            float t1 = nw1 * c1 + (1.f - nw1) * (1.f - c1);
            float t2 = nw2 * c2 + (1.f - nw2) * (1.f - c2);
            sG[tid] = e0c * t1 * t2;
        }
        __syncthreads();
        if (tid < 32) { int base = 144 + (tid << 1); sCoef[0][tid] = sG[base] + sG[base + 1]; }
        __syncthreads();
        if (tid < 32) {
            float v = sCoef[0][30] * sPk[0][tid] + sCoef[0][31] * sPk[1][tid];
            if (tid >= 2) v += sCoef[0][tid - 2];
            d_OC[((size_t)b * SS + t) * 32 + tid] = v;
        }
        e0c = e0n;
    }
#undef PEEK
}

// ============================================================
// Output projection: out[r][v] = oc0 + oc1*siv[v] + sum_h oc[2+h]*syms[h][v]
// grid (512 row tiles, 2 v halves), 256 threads
// All 64 rows' coefficients staged in shared once -> single barrier.
// ============================================================
__global__ __launch_bounds__(256) void k_out(const float* __restrict__ siv,
                                             const float* __restrict__ syms,
                                             float* __restrict__ out) {
    __shared__ float sv[31][256];
    __shared__ float soc[64][32];
    int v0 = blockIdx.y * 256;
    int r0 = blockIdx.x * 64;
    int tid = threadIdx.x;
#pragma unroll
    for (int e = 0; e < 31; e++) {
        int idx = tid + e * 256;
        int h = idx >> 8, v = idx & 255;
        sv[h][v] = (h == 0) ? siv[v0 + v] : syms[(h - 1) * VDIM + v0 + v];
    }
#pragma unroll
    for (int e = 0; e < 8; e++) {
        int idx = tid + e * 256;
        soc[idx >> 5][idx & 31] = d_OC[(size_t)(r0 + (idx >> 5)) * 32 + (idx & 31)];
    }
    __syncthreads();
#pragma unroll 4
    for (int rr = 0; rr < 64; rr++) {
        float acc = soc[rr][0];
        acc += soc[rr][1] * sv[0][tid];
#pragma unroll
        for (int h = 0; h < 30; h++) acc += soc[rr][2 + h] * sv[1 + h][tid];
        out[(size_t)(r0 + rr) * VDIM + v0 + tid] = acc;
    }
}

// ============================================================
extern "C" void kernel_launch(void* const* d_in, const int* in_sizes, int n_in,
                              void* d_out, int out_size) {
    const float* x         = (const float*)d_in[0];
    const float* syms      = (const float*)d_in[1];
    const float* siv       = (const float*)d_in[2];
    const float* sharp     = (const float*)d_in[3];
    const float* pop_w     = (const float*)d_in[4];
    const float* pop_nw    = (const float*)d_in[5];
    const float* pushop_w  = (const float*)d_in[6];
    const float* pushop_nw = (const float*)d_in[7];
    const float* pushfn_w  = (const float*)d_in[8];
    const float* pushfn_nw = (const float*)d_in[9];
    const float* calc_w    = (const float*)d_in[10];
    const float* calc_nw   = (const float*)d_in[11];
    float* out = (float*)d_out;

    k_gram<<<dim3(32, 32), 32>>>(siv, syms);
    k_setup<<<NG, 256>>>(siv, syms, pop_w, pop_nw, pushop_w, pushop_nw,
                         pushfn_w, pushfn_nw, calc_w, calc_nw);
    k_xnorm<<<256, 256>>>(x);
    k_e0<<<512, 256>>>(x);
    k_scan<<<BB, 256>>>(sharp);
    k_out<<<dim3(512, 2), 256>>>(siv, syms, out);
}

// round 9
// speedup vs baseline: 1.3721x; 1.3721x over previous
#include <cuda_runtime.h>
#include <math.h>
#include <stdint.h>

// ---- problem constants ----
#define NG   208      // total gates: pop(8) + pushop(8) + pushfn(128) + calc(64)
#define VDIM 512
#define BB   256
#define SS   128
#define ZO   1e-6f
#define EPS  1e-8f

// ---- device scratch (no allocations allowed; __device__ globals are the
// sanctioned mechanism) ----
__device__ float d_M[32 * 32];                    // Gram of 32-dim basis
__device__ float d_Gn1[NG * 32];                  // basis . w_vec1 / max(||w_vec1||,eps)
__device__ float d_Gn2[NG * 32];                  // basis . w_vec2 / max(||w_vec2||,eps)
__device__ float d_NWv[NG * 3];                   // sigmoid(nw_raw)
__device__ float d_W0T[VDIM * NG];                // w_vec0 normalized, transposed [v][c]
__device__ float d_invnx[BB * SS];                // 1/max(||x_row||,eps)
__device__ float d_E0[(size_t)SS * BB * NG];      // precomputed vec0 interp term
__device__ float d_OC[(size_t)BB * SS * 32];      // output coefficients

// ---- f32x2 packed helpers (Blackwell FFMA2: only reachable via PTX) ----
__device__ __forceinline__ unsigned long long ffma2(unsigned long long a,
                                                    unsigned long long b,
                                                    unsigned long long c) {
    unsigned long long d;
    asm("fma.rn.f32x2 %0, %1, %2, %3;" : "=l"(d) : "l"(a), "l"(b), "l"(c));
    return d;
}
__device__ __forceinline__ unsigned long long pack2(float lo, float hi) {
    unsigned long long r;
    asm("mov.b64 %0, {%1, %2};" : "=l"(r) : "f"(lo), "f"(hi));
    return r;
}
__device__ __forceinline__ void unpack2(unsigned long long v, float& lo, float& hi) {
    asm("mov.b64 {%0, %1}, %2;" : "=f"(lo), "=f"(hi) : "l"(v));
}

// ============================================================
// Gram matrix of the 32-dim basis: b0 = ones, b1 = siv, b2+h = syms[h]
// ============================================================
__global__ void k_gram(const float* __restrict__ siv, const float* __restrict__ syms) {
    int i = blockIdx.x, j = blockIdx.y;
    int lane = threadIdx.x;
    float s = 0.f;
    for (int v = lane; v < VDIM; v += 32) {
        float bi = (i == 0) ? 1.f : ((i == 1) ? siv[v] : syms[(i - 2) * VDIM + v]);
        float bj = (j == 0) ? 1.f : ((j == 1) ? siv[v] : syms[(j - 2) * VDIM + v]);
        s += bi * bj;
    }
    for (int o = 16; o; o >>= 1) s += __shfl_down_sync(0xffffffffu, s, o);
    if (lane == 0) d_M[i * 32 + j] = s;
}

// ============================================================
// Per-gate preprocessing
// ============================================================
__global__ void k_setup(const float* __restrict__ siv, const float* __restrict__ syms,
                        const float* __restrict__ pop_w, const float* __restrict__ pop_nw,
                        const float* __restrict__ pushop_w, const float* __restrict__ pushop_nw,
                        const float* __restrict__ pushfn_w, const float* __restrict__ pushfn_nw,
                        const float* __restrict__ calc_w, const float* __restrict__ calc_nw) {
    int c = blockIdx.x;
    const float* wb;
    const float* nb;
    if (c < 8)        { wb = pop_w    + (size_t)c * 3 * VDIM;          nb = pop_nw    + (size_t)c * 3; }
    else if (c < 16)  { wb = pushop_w + (size_t)(c - 8) * 3 * VDIM;    nb = pushop_nw + (size_t)(c - 8) * 3; }
    else if (c < 144) { wb = pushfn_w + (size_t)(c - 16) * 3 * VDIM;   nb = pushfn_nw + (size_t)(c - 16) * 3; }
    else              { wb = calc_w   + (size_t)(c - 144) * 3 * VDIM;  nb = calc_nw   + (size_t)(c - 144) * 3; }

    __shared__ float sg[67];
    int warp = threadIdx.x >> 5, lane = threadIdx.x & 31;
    for (int job = warp; job < 67; job += 8) {
        const float* w;
        int bi;
        if (job < 64) { bi = job >> 1; w = wb + ((job & 1) + 1) * VDIM; }
        else          { bi = -1;       w = wb + (job - 64) * VDIM; }
        float s = 0.f;
        for (int v = lane; v < VDIM; v += 32) {
            float wv = w[v];
            float bv = (bi < 0) ? wv
                     : ((bi == 0) ? 1.f : ((bi == 1) ? siv[v] : syms[(bi - 2) * VDIM + v]));
            s += wv * bv;
        }
        for (int o = 16; o; o >>= 1) s += __shfl_down_sync(0xffffffffu, s, o);
        if (!lane) sg[job] = s;
    }
    __syncthreads();
    if (threadIdx.x < 64) {
        int bi = threadIdx.x >> 1, vecsel = threadIdx.x & 1;
        float n = fmaxf(sqrtf(sg[65 + vecsel]), EPS);
        float g = sg[threadIdx.x] / n;
        if (vecsel == 0) d_Gn1[c * 32 + bi] = g;
        else             d_Gn2[c * 32 + bi] = g;
    }
    if (threadIdx.x < 3) d_NWv[c * 3 + threadIdx.x] = 1.f / (1.f + expf(-nb[threadIdx.x]));
    float n0 = fmaxf(sqrtf(sg[64]), EPS);
    for (int v = threadIdx.x; v < VDIM; v += blockDim.x)
        d_W0T[(size_t)v * NG + c] = wb[v] / n0;
}

// ============================================================
// Row norms of x: one warp per row
// ============================================================
__global__ void k_xnorm(const float* __restrict__ x) {
    int wg = (blockIdx.x * blockDim.x + threadIdx.x) >> 5;
    int lane = threadIdx.x & 31;
    int nwarps = (gridDim.x * blockDim.x) >> 5;
    for (int r = wg; r < BB * SS; r += nwarps) {
        const float* xr = x + (size_t)r * VDIM;
        float s = 0.f;
        for (int v = lane; v < VDIM; v += 32) { float t = xr[v]; s += t * t; }
        for (int o = 16; o; o >>= 1) s += __shfl_down_sync(0xffffffffu, s, o);
        if (!lane) d_invnx[r] = 1.f / fmaxf(sqrtf(s), EPS);
    }
}

// ============================================================
// E0 GEMM via packed FFMA2 (f32x2): 2 MACs per instruction, IEEE-exact fp32.
// Row-pairs packed: x staged TRANSPOSED in shared so row pairs are contiguous.
// grid = 512 blocks (64 rows each), 256 threads
// ============================================================
__global__ __launch_bounds__(256) void k_e0(const float* __restrict__ x) {
    __shared__ __align__(8) float xs_T[32][66];   // [kk][row], stride 66: even (8B ok), 2-way store conflict only
    __shared__ float ws[32][224];                 // [kk][c], cols 208..223 zero pad
    __shared__ float snw[NG];
    int tid = threadIdx.x;
    int m0 = blockIdx.x * 64;
    if (tid < NG) snw[tid] = d_NWv[tid * 3];
#pragma unroll
    for (int e = 0; e < 2; e++) {
        int idx = tid + e * 256;
        if (idx < 512) { int kk = idx >> 4, cc = 208 + (idx & 15); ws[kk][cc] = 0.f; }
    }
    unsigned long long acc2[4][7];
#pragma unroll
    for (int up = 0; up < 4; up++)
#pragma unroll
        for (int cu = 0; cu < 7; cu++) acc2[up][cu] = 0ull;
    int tr = tid >> 5, tc = tid & 31;   // warp tr handles rows tr*8..tr*8+7

    for (int k0 = 0; k0 < VDIM; k0 += 32) {
        __syncthreads();
        // stage x transposed: warp reads 128B coalesced per row, writes column
#pragma unroll
        for (int e = 0; e < 8; e++) {
            int r = tr + e * 8;         // 0..63
            int kk = tc;
            int m = m0 + r;
            int b = m & 255, s = m >> 8;
            xs_T[kk][r] = x[((size_t)(b * SS + s)) * VDIM + k0 + kk];
        }
#pragma unroll
        for (int e = 0; e < 26; e++) {
            int idx = tid + e * 256;
            int kk = idx / 208, c = idx % 208;
            ws[kk][c] = d_W0T[(size_t)(k0 + kk) * NG + c];
        }
        __syncthreads();
#pragma unroll 4
        for (int kk = 0; kk < 32; kk++) {
            unsigned long long xp[4];
#pragma unroll
            for (int up = 0; up < 4; up++)
                xp[up] = *(const unsigned long long*)&xs_T[kk][tr * 8 + 2 * up]; // broadcast
#pragma unroll
            for (int cu = 0; cu < 7; cu++) {
                float w = ws[kk][tc + cu * 32];
                unsigned long long wd = pack2(w, w);
#pragma unroll
                for (int up = 0; up < 4; up++)
                    acc2[up][cu] = ffma2(xp[up], wd, acc2[up][cu]);
            }
        }
    }
    __syncthreads();
#pragma unroll
    for (int up = 0; up < 4; up++) {
        int mlo = m0 + tr * 8 + 2 * up;
        int mhi = mlo + 1;
        float inx0 = d_invnx[(mlo & 255) * SS + (mlo >> 8)];
        float inx1 = d_invnx[(mhi & 255) * SS + (mhi >> 8)];
#pragma unroll
        for (int cu = 0; cu < 7; cu++) {
            int c = tc + cu * 32;
            if (c < NG) {
                float lo, hi;
                unpack2(acc2[up][cu], lo, hi);
                float nw = snw[c];
                float c0 = fabsf(lo * inx0);
                float c1 = fabsf(hi * inx1);
                d_E0[(size_t)mlo * NG + c] = nw * c0 + (1.f - nw) * (1.f - c0);
                d_E0[(size_t)mhi * NG + c] = nw * c1 + (1.f - nw) * (1.f - c1);
            }
        }
    }
}

// ============================================================
// Sequential scan in 32-dim coefficient space.
// One block per batch lane, 256 threads, 128 steps.
// G in shared (interleaved float2, conflict-free), padded Gram (kills the
// 32-way bank conflict of the norm loop), double-buffered stacks,
// warp-shuffle reductions: 6 barriers per step.
// ============================================================
#define SCAN_SMEM_FLOATS (13312 + 1056 + 512 + 64 + 64 + 208 + 16 + 2 + 4)

__global__ __launch_bounds__(256, 2) void k_scan(const float* __restrict__ sharp_in) {
    const int b = blockIdx.x;
    const int tid = threadIdx.x;
    extern __shared__ float smem[];
    float2* G12  = (float2*)smem;                 // [32][208] interleaved (G1,G2)
    float*  sM   = smem + 13312;                  // [32][33] padded Gram
    float*  sAa  = sM + 1056;                     // stacks double buffer [2][2][4][32]
    float*  sPv  = sAa + 512;                     // push-value coefs [2][32]
    float2* sPk2 = (float2*)(sPv + 64);           // peek coefs, (stack0,stack1) pairs [32]
    float*  sG   = (float*)(sPk2 + 32);           // gate activations [208]
    float*  sPp  = sG + 208;                      // pointer double buffer [2][2][4]
    float*  sNp  = sPp + 16;                      // peek norms [2]
    float*  sProb= sNp + 2;                       // [k][0]=P(pop), [k][1]=P(push)

#define SA(buf, k, d, i) sAa[(((buf) * 2 + (k)) * 4 + (d)) * 32 + (i)]
#define SP(buf, k, d)    sPp[((buf) * 2 + (k)) * 4 + (d)]

    // ---- stage per-gate tables ----
    for (int idx = tid; idx < NG * 32; idx += 256) {
        int c = idx >> 5, i = idx & 31;
        G12[i * 208 + c] = make_float2(d_Gn1[idx], d_Gn2[idx]);
    }
    for (int idx = tid; idx < 1024; idx += 256)
        sM[(idx >> 5) * 33 + (idx & 31)] = d_M[idx];

    float nw1 = 0.f, nw2 = 0.f;
    if (tid < NG) { nw1 = d_NWv[tid * 3 + 1]; nw2 = d_NWv[tid * 3 + 2]; }

    // ---- init stacks (buf 0): slots = ZO*ones, slot1 = siv (hard push), ptr@1 ----
    {
        int k = tid >> 7, d = (tid >> 5) & 3, i = tid & 31;
        SA(0, k, d, i) = (d == 1) ? ((i == 1) ? 1.f : 0.f) : ((i == 0) ? ZO : 0.f);
        if (tid < 8) SP(0, tid >> 2, tid & 3) = ((tid & 3) == 1) ? 1.f : 0.f;
    }
    const float sh0 = sharp_in[0], sh1 = sharp_in[1];
    int buf = 0;
    __syncthreads();

    // ---- initial peek ----
    {
        float mypk = 0.f;
        if (tid < 64) {
            int k = tid >> 5, i = tid & 31;
            float s = 0.f;
#pragma unroll
            for (int d = 0; d < 4; d++) s += SP(buf, k, d) * SA(buf, k, d, i);
            ((float*)&sPk2[i])[k] = s;
            mypk = s;
        }
        __syncthreads();
        if (tid < 64) {
            int k = tid >> 5, i = tid & 31;
            float q = 0.f;
#pragma unroll
            for (int j = 0; j < 32; j++) q = fmaf(sM[i * 33 + j], ((float*)&sPk2[j])[k], q);
            float part = mypk * q;
            for (int o = 16; o; o >>= 1) part += __shfl_down_sync(0xffffffffu, part, o);
            if (i == 0) sNp[k] = sqrtf(fmaxf(part, 0.f));
        }
        __syncthreads();
    }

    float e0c = (tid < NG) ? d_E0[((size_t)0 * BB + b) * NG + tid] : 0.f;

    for (int t = 0; t < SS; t++) {
        float e0n = 0.f;
        if (tid < NG && t < SS - 1) e0n = d_E0[((size_t)(t + 1) * BB + b) * NG + tid];

        // ---- phase A gates (tid<144) with current peeks ----
        if (tid < 144) {
            float inv0 = 1.f / fmaxf(sNp[0], EPS);
            float inv1 = 1.f / fmaxf(sNp[1], EPS);
            float d1a = 0.f, d1b = 0.f, d2a = 0.f, d2b = 0.f;
#pragma unroll
            for (int i = 0; i < 32; i += 2) {
                float2 pa = sPk2[i];
                float2 ga = G12[i * 208 + tid];
                d1a = fmaf(pa.x, ga.x, d1a); d2a = fmaf(pa.y, ga.y, d2a);
                float2 pb = sPk2[i + 1];
                float2 gb = G12[(i + 1) * 208 + tid];
                d1b = fmaf(pb.x, gb.x, d1b); d2b = fmaf(pb.y, gb.y, d2b);
            }
            float c1 = fabsf(d1a + d1b) * inv0;
            float c2 = fabsf(d2a + d2b) * inv1;
            float t1 = nw1 * c1 + (1.f - nw1) * (1.f - c1);
            float t2 = nw2 * c2 + (1.f - nw2) * (1.f - c2);
            sG[tid] = e0c * t1 * t2;
        }
        __syncthreads();                              // bar1

        // ---- push coefs + push value (warps 0,1 via shfl); probs (warp 2 lanes 0,1) ----
        if (tid < 64) {
            int k = tid >> 5, cc = tid & 31;
            int base = 16 + (k << 6) + (cc << 1);
            float cf = sG[base] + sG[base + 1];
            float cf30 = __shfl_sync(0xffffffffu, cf, 30);
            float cf31 = __shfl_sync(0xffffffffu, cf, 31);
            float cfm2 = __shfl_up_sync(0xffffffffu, cf, 2);
            float2 pk = sPk2[cc];
            float v = cf30 * pk.x + cf31 * pk.y + ((cc >= 2) ? cfm2 : 0.f);
            sPv[k * 32 + cc] = v;
        } else if (tid < 66) {
            int k = tid - 64;
            float sh = k ? sh1 : sh0;
            float pp = fmaxf(sG[k * 4 + 0], sG[k * 4 + 1]) * sh;
            float pn = fmaxf(sG[k * 4 + 2], sG[k * 4 + 3]) * sh;
            float m = fmaxf(pp, pn);
            float ea = expf(pp - m), eb = expf(pn - m);
            sProb[k * 2 + 0] = ea / (ea + eb);
            float qp = fmaxf(sG[8 + k * 4 + 0], sG[8 + k * 4 + 1]) * sh;
            float qn = fmaxf(sG[8 + k * 4 + 2], sG[8 + k * 4 + 3]) * sh;
            float m2 = fmaxf(qp, qn);
            float ec = expf(qp - m2), ed = expf(qn - m2);
            sProb[k * 2 + 1] = ec / (ec + ed);
        }
        __syncthreads();                              // bar2

        // ---- stack update: pop_or_nop then push_or_nop, double-buffered ----
        {
            int k = tid >> 7, d = (tid >> 5) & 3, i = tid & 31;
            float a   = SA(buf, k, d, i);
            float pd  = SP(buf, k, d);
            float pdp = SP(buf, k, (d + 1) & 3);
            float pdm = SP(buf, k, (d - 1) & 3);
            float pop  = sProb[k * 2 + 0];
            float push = sProb[k * 2 + 1];
            float pv = sPv[k * 32 + i];
            float ps = a * (1.f - pd) + ((i == 0) ? ZO : 0.f) * pd;
            float s1 = ps * pop + a * (1.f - pop);
            float prold = pd * pop + pdm * (1.f - pop);   // roll(p_after_pop, +1)[d]
            float p1d   = pdp * pop + pd * (1.f - pop);   // p_after_pop[d]
            float ps2 = s1 * (1.f - prold) + pv * prold;
            float s2 = ps2 * push + s1 * (1.f - push);
            float p2 = prold * push + p1d * (1.f - push);
            SA(buf ^ 1, k, d, i) = s2;
            if (i == 0) SP(buf ^ 1, k, d) = p2;
        }
        __syncthreads();                              // bar3
        buf ^= 1;

        // ---- new peeks ----
        float mypk = 0.f;
        if (tid < 64) {
            int k = tid >> 5, i = tid & 31;
            float s = 0.f;
#pragma unroll
            for (int d = 0; d < 4; d++) s += SP(buf, k, d) * SA(buf, k, d, i);
            ((float*)&sPk2[i])[k] = s;
            mypk = s;
        }
        __syncthreads();                              // bar4
        if (tid < 64) {
            int k = tid >> 5, i = tid & 31;
            float q = 0.f;
#pragma unroll
            for (int j = 0; j < 32; j++) q = fmaf(sM[i * 33 + j], ((float*)&sPk2[j])[k], q);
            float part = mypk * q;
            for (int o = 16; o; o >>= 1) part += __shfl_down_sync(0xffffffffu, part, o);
            if (i == 0) sNp[k] = sqrtf(fmaxf(part, 0.f));
        }
        __syncthreads();                              // bar5

        // ---- phase B: calc gates with new peeks ----
        if (tid >= 144 && tid < NG) {
            float inv0 = 1.f / fmaxf(sNp[0], EPS);
            float inv1 = 1.f / fmaxf(sNp[1], EPS);
            float d1a = 0.f, d1b = 0.f, d2a = 0.f, d2b = 0.f;
#pragma unroll
            for (int i = 0; i < 32; i += 2) {
                float2 pa = sPk2[i];
                float2 ga = G12[i * 208 + tid];
                d1a = fmaf(pa.x, ga.x, d1a); d2a = fmaf(pa.y, ga.y, d2a);
                float2 pb = sPk2[i + 1];
                float2 gb = G12[(i + 1) * 208 + tid];
                d1b = fmaf(pb.x, gb.x, d1b); d2b = fmaf(pb.y, gb.y, d2b);
            }
            float c1 = fabsf(d1a + d1b) * inv0;
            float c2 = fabsf(d2a + d2b) * inv1;
            float t1 = nw1 * c1 + (1.f - nw1) * (1.f - c1);
            float t2 = nw2 * c2 + (1.f - nw2) * (1.f - c2);
            sG[tid] = e0c * t1 * t2;
        }
        __syncthreads();                              // bar6

        // ---- output coefficients (warp 0 via shfl; safe vs next phase A: disjoint sG) ----
        if (tid < 32) {
            int base = 144 + (tid << 1);
            float cf = sG[base] + sG[base + 1];
            float cf30 = __shfl_sync(0xffffffffu, cf, 30);
            float cf31 = __shfl_sync(0xffffffffu, cf, 31);
            float cfm2 = __shfl_up_sync(0xffffffffu, cf, 2);
            float2 pk = sPk2[tid];
            float v = cf30 * pk.x + cf31 * pk.y + ((tid >= 2) ? cfm2 : 0.f);
            d_OC[((size_t)b * SS + t) * 32 + tid] = v;
        }
        e0c = e0n;
    }
#undef SA
#undef SP
}

// ============================================================
// Output projection: out[r][v] = oc0 + oc1*siv[v] + sum_h oc[2+h]*syms[h][v]
// ============================================================
__global__ __launch_bounds__(256) void k_out(const float* __restrict__ siv,
                                             const float* __restrict__ syms,
                                             float* __restrict__ out) {
    __shared__ float sv[31][256];
    __shared__ float soc[64][32];
    int v0 = blockIdx.y * 256;
    int r0 = blockIdx.x * 64;
    int tid = threadIdx.x;
#pragma unroll
    for (int e = 0; e < 31; e++) {
        int idx = tid + e * 256;
        int h = idx >> 8, v = idx & 255;
        sv[h][v] = (h == 0) ? siv[v0 + v] : syms[(h - 1) * VDIM + v0 + v];
    }
#pragma unroll
    for (int e = 0; e < 8; e++) {
        int idx = tid + e * 256;
        soc[idx >> 5][idx & 31] = d_OC[(size_t)(r0 + (idx >> 5)) * 32 + (idx & 31)];
    }
    __syncthreads();
#pragma unroll 4
    for (int rr = 0; rr < 64; rr++) {
        float acc = soc[rr][0];
        acc += soc[rr][1] * sv[0][tid];
#pragma unroll
        for (int h = 0; h < 30; h++) acc += soc[rr][2 + h] * sv[1 + h][tid];
        out[(size_t)(r0 + rr) * VDIM + v0 + tid] = acc;
    }
}

// ============================================================
extern "C" void kernel_launch(void* const* d_in, const int* in_sizes, int n_in,
                              void* d_out, int out_size) {
    const float* x         = (const float*)d_in[0];
    const float* syms      = (const float*)d_in[1];
    const float* siv       = (const float*)d_in[2];
    const float* sharp     = (const float*)d_in[3];
    const float* pop_w     = (const float*)d_in[4];
    const float* pop_nw    = (const float*)d_in[5];
    const float* pushop_w  = (const float*)d_in[6];
    const float* pushop_nw = (const float*)d_in[7];
    const float* pushfn_w  = (const float*)d_in[8];
    const float* pushfn_nw = (const float*)d_in[9];
    const float* calc_w    = (const float*)d_in[10];
    const float* calc_nw   = (const float*)d_in[11];
    float* out = (float*)d_out;

    const int scan_smem = SCAN_SMEM_FLOATS * (int)sizeof(float);
    cudaFuncSetAttribute(k_scan, cudaFuncAttributeMaxDynamicSharedMemorySize, scan_smem);

    k_gram<<<dim3(32, 32), 32>>>(siv, syms);
    k_setup<<<NG, 256>>>(siv, syms, pop_w, pop_nw, pushop_w, pushop_nw,
                         pushfn_w, pushfn_nw, calc_w, calc_nw);
    k_xnorm<<<256, 256>>>(x);
    k_e0<<<512, 256>>>(x);
    k_scan<<<BB, 256, scan_smem>>>(sharp);
    k_out<<<dim3(512, 2), 256>>>(siv, syms, out);
}

// round 14
// speedup vs baseline: 1.8278x; 1.3321x over previous
#include <cuda_runtime.h>
#include <cuda_bf16.h>
#include <math.h>
#include <stdint.h>

// ---- problem constants ----
#define NG   208      // total gates: pop(8) + pushop(8) + pushfn(128) + calc(64)
#define VDIM 512
#define BB   256
#define SS   128
#define ZO   1e-6f
#define EPS  1e-8f

// ---- device scratch (no allocations allowed) ----
__device__ float d_M[32 * 32];                    // Gram of 32-dim basis
__device__ float d_Gn1[NG * 32];                  // basis . w_vec1 / max(||w_vec1||,eps)
__device__ float d_Gn2[NG * 32];                  // basis . w_vec2 / max(||w_vec2||,eps)
__device__ float d_NWv[NG * 3];                   // sigmoid(nw_raw)
__device__ __nv_bfloat16 d_BThi[(size_t)VDIM * NG]; // normalized w0 hi bf16, TRANSPOSED [v][c]
__device__ __nv_bfloat16 d_BTlo[(size_t)VDIM * NG]; // residual lo bf16, TRANSPOSED [v][c]
__device__ float d_invnx[BB * SS];                // 1/max(||x_row||,eps)
__device__ float d_E0[(size_t)SS * BB * NG];      // precomputed vec0 interp term
__device__ float d_OC[(size_t)BB * SS * 32];      // output coefficients

// ---- warp-MMA helpers (baseline ISA: sm_80+, compiles for plain sm_103) ----
__device__ __forceinline__ uint32_t smem_u32(const void* p) {
    uint32_t a;
    asm("{ .reg .u64 t; cvta.to.shared.u64 t, %1; cvt.u32.u64 %0, t; }" : "=r"(a) : "l"(p));
    return a;
}
__device__ __forceinline__ void ldsm4(uint32_t* a, uint32_t addr) {
    asm volatile("ldmatrix.sync.aligned.m8n8.x4.shared.b16 {%0,%1,%2,%3}, [%4];"
        : "=r"(a[0]), "=r"(a[1]), "=r"(a[2]), "=r"(a[3]) : "r"(addr));
}
__device__ __forceinline__ void ldsm2t(uint32_t* b, uint32_t addr) {
    asm volatile("ldmatrix.sync.aligned.m8n8.x2.trans.shared.b16 {%0,%1}, [%2];"
        : "=r"(b[0]), "=r"(b[1]) : "r"(addr));
}
__device__ __forceinline__ void mma_bf16(float* d, const uint32_t* a, const uint32_t* b) {
    asm volatile("mma.sync.aligned.m16n8k16.row.col.f32.bf16.bf16.f32 "
        "{%0,%1,%2,%3}, {%4,%5,%6,%7}, {%8,%9}, {%0,%1,%2,%3};"
        : "+f"(d[0]), "+f"(d[1]), "+f"(d[2]), "+f"(d[3])
        : "r"(a[0]), "r"(a[1]), "r"(a[2]), "r"(a[3]), "r"(b[0]), "r"(b[1]));
}

// ============================================================
// Gram matrix of the 32-dim basis: b0 = ones, b1 = siv, b2+h = syms[h]
// ============================================================
__global__ void k_gram(const float* __restrict__ siv, const float* __restrict__ syms) {
    int i = blockIdx.x, j = blockIdx.y;
    int lane = threadIdx.x;
    float s = 0.f;
    for (int v = lane; v < VDIM; v += 32) {
        float bi = (i == 0) ? 1.f : ((i == 1) ? siv[v] : syms[(i - 2) * VDIM + v]);
        float bj = (j == 0) ? 1.f : ((j == 1) ? siv[v] : syms[(j - 2) * VDIM + v]);
        s += bi * bj;
    }
    for (int o = 16; o; o >>= 1) s += __shfl_down_sync(0xffffffffu, s, o);
    if (lane == 0) d_M[i * 32 + j] = s;
}

// ============================================================
// Per-gate preprocessing (emits TRANSPOSED bf16 hi/lo split of normalized w0)
// ============================================================
__global__ void k_setup(const float* __restrict__ siv, const float* __restrict__ syms,
                        const float* __restrict__ pop_w, const float* __restrict__ pop_nw,
                        const float* __restrict__ pushop_w, const float* __restrict__ pushop_nw,
                        const float* __restrict__ pushfn_w, const float* __restrict__ pushfn_nw,
                        const float* __restrict__ calc_w, const float* __restrict__ calc_nw) {
    int c = blockIdx.x;
    const float* wb;
    const float* nb;
    if (c < 8)        { wb = pop_w    + (size_t)c * 3 * VDIM;          nb = pop_nw    + (size_t)c * 3; }
    else if (c < 16)  { wb = pushop_w + (size_t)(c - 8) * 3 * VDIM;    nb = pushop_nw + (size_t)(c - 8) * 3; }
    else if (c < 144) { wb = pushfn_w + (size_t)(c - 16) * 3 * VDIM;   nb = pushfn_nw + (size_t)(c - 16) * 3; }
    else              { wb = calc_w   + (size_t)(c - 144) * 3 * VDIM;  nb = calc_nw   + (size_t)(c - 144) * 3; }

    __shared__ float sg[67];
    int warp = threadIdx.x >> 5, lane = threadIdx.x & 31;
    for (int job = warp; job < 67; job += 8) {
        const float* w;
        int bi;
        if (job < 64) { bi = job >> 1; w = wb + ((job & 1) + 1) * VDIM; }
        else          { bi = -1;       w = wb + (job - 64) * VDIM; }
        float s = 0.f;
        for (int v = lane; v < VDIM; v += 32) {
            float wv = w[v];
            float bv = (bi < 0) ? wv
                     : ((bi == 0) ? 1.f : ((bi == 1) ? siv[v] : syms[(bi - 2) * VDIM + v]));
            s += wv * bv;
        }
        for (int o = 16; o; o >>= 1) s += __shfl_down_sync(0xffffffffu, s, o);
        if (!lane) sg[job] = s;
    }
    __syncthreads();
    if (threadIdx.x < 64) {
        int bi = threadIdx.x >> 1, vecsel = threadIdx.x & 1;
        float n = fmaxf(sqrtf(sg[65 + vecsel]), EPS);
        float g = sg[threadIdx.x] / n;
        if (vecsel == 0) d_Gn1[c * 32 + bi] = g;
        else             d_Gn2[c * 32 + bi] = g;
    }
    if (threadIdx.x < 3) d_NWv[c * 3 + threadIdx.x] = 1.f / (1.f + expf(-nb[threadIdx.x]));
    float n0 = fmaxf(sqrtf(sg[64]), EPS);
    for (int v = threadIdx.x; v < VDIM; v += blockDim.x) {
        float val = wb[v] / n0;
        __nv_bfloat16 h = __float2bfloat16(val);
        d_BThi[(size_t)v * NG + c] = h;
        d_BTlo[(size_t)v * NG + c] = __float2bfloat16(val - __bfloat162float(h));
    }
}

// ============================================================
// Row norms of x: one warp per row
// ============================================================
__global__ void k_xnorm(const float* __restrict__ x) {
    int wg = (blockIdx.x * blockDim.x + threadIdx.x) >> 5;
    int lane = threadIdx.x & 31;
    int nwarps = (gridDim.x * blockDim.x) >> 5;
    for (int r = wg; r < BB * SS; r += nwarps) {
        const float* xr = x + (size_t)r * VDIM;
        float s = 0.f;
        for (int v = lane; v < VDIM; v += 32) { float t = xr[v]; s += t * t; }
        for (int o = 16; o; o >>= 1) s += __shfl_down_sync(0xffffffffu, s, o);
        if (!lane) d_invnx[r] = 1.f / fmaxf(sqrtf(s), EPS);
    }
}

// ============================================================
// E0 GEMM via mma.sync bf16 hi/lo split (fp32 acc):
//   D = Ahi*Bhi + Ahi*Blo + Alo*Bhi
// 256 blocks, 256 threads (8 warps). Tile M=128/block, N=208 full, K chunks of 32.
// Warp w owns rows w*16..w*16+15, acc[26][4] fp32 (m16n8 fragments).
// A smem [128][40] bf16 (conflict-free ldmatrix), B smem [32][216] bf16 k-major
// (ldmatrix.x2.trans -> col-layout fragment, conflict-free).
// ============================================================
__global__ __launch_bounds__(256) void k_e0(const float* __restrict__ x) {
    __shared__ __align__(16) __nv_bfloat16 As_hi[128 * 40];
    __shared__ __align__(16) __nv_bfloat16 As_lo[128 * 40];
    __shared__ __align__(16) __nv_bfloat16 Bs_hi[32 * 216];
    __shared__ __align__(16) __nv_bfloat16 Bs_lo[32 * 216];

    const int tid = threadIdx.x;
    const int wid = tid >> 5, lane = tid & 31;
    const int m0 = blockIdx.x * 128;

    const uint32_t uAh = smem_u32(As_hi), uAl = smem_u32(As_lo);
    const uint32_t uBh = smem_u32(Bs_hi), uBl = smem_u32(Bs_lo);

    float acc[26][4];
#pragma unroll
    for (int nt = 0; nt < 26; nt++)
#pragma unroll
        for (int q = 0; q < 4; q++) acc[nt][q] = 0.f;

    // per-thread A staging coords: 2 threads per row, 4 float4 each
    const int ar = tid >> 1, aq = tid & 1;
    const int am = m0 + ar;
    const float* xrow = x + ((size_t)((am & 255) * SS + (am >> 8))) * VDIM + aq * 16;

    for (int ch = 0; ch < 16; ch++) {
        const int k0 = ch * 32;
        __syncthreads();
        // ---- stage A: fp32 -> bf16 hi/lo ----
        {
            uint32_t* hrow = (uint32_t*)(As_hi + ar * 40 + aq * 16);
            uint32_t* lrow = (uint32_t*)(As_lo + ar * 40 + aq * 16);
#pragma unroll
            for (int i = 0; i < 4; i++) {
                float4 v = *(const float4*)(xrow + k0 + i * 4);
                __nv_bfloat16 h0 = __float2bfloat16(v.x);
                __nv_bfloat16 h1 = __float2bfloat16(v.y);
                __nv_bfloat16 h2 = __float2bfloat16(v.z);
                __nv_bfloat16 h3 = __float2bfloat16(v.w);
                __nv_bfloat16 l0 = __float2bfloat16(v.x - __bfloat162float(h0));
                __nv_bfloat16 l1 = __float2bfloat16(v.y - __bfloat162float(h1));
                __nv_bfloat16 l2 = __float2bfloat16(v.z - __bfloat162float(h2));
                __nv_bfloat16 l3 = __float2bfloat16(v.w - __bfloat162float(h3));
                hrow[i * 2 + 0] = (uint32_t)__bfloat16_as_ushort(h0) | ((uint32_t)__bfloat16_as_ushort(h1) << 16);
                hrow[i * 2 + 1] = (uint32_t)__bfloat16_as_ushort(h2) | ((uint32_t)__bfloat16_as_ushort(h3) << 16);
                lrow[i * 2 + 0] = (uint32_t)__bfloat16_as_ushort(l0) | ((uint32_t)__bfloat16_as_ushort(l1) << 16);
                lrow[i * 2 + 1] = (uint32_t)__bfloat16_as_ushort(l2) | ((uint32_t)__bfloat16_as_ushort(l3) << 16);
            }
        }
        // ---- stage B: coalesced uint32 copies of transposed weights ----
        // 32 k-rows x 104 u32 = 3328 u32 per buffer -> exactly 13 iters x 256 thr
        {
            const uint32_t* bhr = (const uint32_t*)d_BThi;   // [512][104] u32
            const uint32_t* blr = (const uint32_t*)d_BTlo;
            uint32_t* bsh = (uint32_t*)Bs_hi;                // [32][108] u32
            uint32_t* bsl = (uint32_t*)Bs_lo;
#pragma unroll
            for (int i = 0; i < 13; i++) {
                int idx = tid + i * 256;                     // < 3328
                int kk = idx / 104, j = idx - kk * 104;
                bsh[kk * 108 + j] = bhr[(size_t)(k0 + kk) * 104 + j];
                bsl[kk * 108 + j] = blr[(size_t)(k0 + kk) * 104 + j];
            }
        }
        __syncthreads();
        // ---- compute: 2 k-sub x 26 n-tiles x 3 mmas ----
#pragma unroll
        for (int ksub = 0; ksub < 32; ksub += 16) {
            uint32_t ah[4], al[4];
            uint32_t aoff = ((uint32_t)((wid * 16 + (lane & 15)) * 40 + ksub + ((lane >> 4) << 3))) * 2;
            ldsm4(ah, uAh + aoff);
            ldsm4(al, uAl + aoff);
            uint32_t brow = ((uint32_t)((ksub + (lane & 15)) * 216)) * 2;
#pragma unroll
            for (int nt = 0; nt < 26; nt++) {
                uint32_t bh[2], bl[2];
                uint32_t boff = brow + nt * 16;
                ldsm2t(bh, uBh + boff);
                ldsm2t(bl, uBl + boff);
                mma_bf16(acc[nt], ah, bh);
                mma_bf16(acc[nt], ah, bl);
                mma_bf16(acc[nt], al, bh);
            }
        }
    }

    // ---- epilogue: |cos| -> NAND interp, write d_E0 ----
    const int mA = m0 + wid * 16 + (lane >> 2);
    const int mB = mA + 8;
    const float inxA = d_invnx[(mA & 255) * SS + (mA >> 8)];
    const float inxB = d_invnx[(mB & 255) * SS + (mB >> 8)];
    float* eA = &d_E0[(size_t)mA * NG];
    float* eB = &d_E0[(size_t)mB * NG];
    const int c0 = (lane & 3) * 2;
#pragma unroll
    for (int nt = 0; nt < 26; nt++) {
        int c = nt * 8 + c0;
        float nw0 = d_NWv[c * 3];
        float nw1 = d_NWv[(c + 1) * 3];
        float a0 = fabsf(acc[nt][0] * inxA);
        float a1 = fabsf(acc[nt][1] * inxA);
        float b0 = fabsf(acc[nt][2] * inxB);
        float b1 = fabsf(acc[nt][3] * inxB);
        eA[c]     = nw0 * a0 + (1.f - nw0) * (1.f - a0);
        eA[c + 1] = nw1 * a1 + (1.f - nw1) * (1.f - a1);
        eB[c]     = nw0 * b0 + (1.f - nw0) * (1.f - b0);
        eB[c + 1] = nw1 * b1 + (1.f - nw1) * (1.f - b1);
    }
}

// ============================================================
// Sequential scan in 32-dim coefficient space (unchanged from R9-passing).
// ============================================================
#define SCAN_SMEM_FLOATS (13312 + 1056 + 512 + 64 + 64 + 208 + 16 + 2 + 4)

__global__ __launch_bounds__(256, 2) void k_scan(const float* __restrict__ sharp_in) {
    const int b = blockIdx.x;
    const int tid = threadIdx.x;
    extern __shared__ float smem[];
    float2* G12  = (float2*)smem;                 // [32][208] interleaved (G1,G2)
    float*  sM   = smem + 13312;                  // [32][33] padded Gram
    float*  sAa  = sM + 1056;                     // stacks double buffer [2][2][4][32]
    float*  sPv  = sAa + 512;                     // push-value coefs [2][32]
    float2* sPk2 = (float2*)(sPv + 64);           // peek coefs (stack0,stack1) [32]
    float*  sG   = (float*)(sPk2 + 32);           // gate activations [208]
    float*  sPp  = sG + 208;                      // pointer double buffer [2][2][4]
    float*  sNp  = sPp + 16;                      // peek norms [2]
    float*  sProb= sNp + 2;

#define SA(buf, k, d, i) sAa[(((buf) * 2 + (k)) * 4 + (d)) * 32 + (i)]
#define SP(buf, k, d)    sPp[((buf) * 2 + (k)) * 4 + (d)]

    for (int idx = tid; idx < NG * 32; idx += 256) {
        int c = idx >> 5, i = idx & 31;
        G12[i * 208 + c] = make_float2(d_Gn1[idx], d_Gn2[idx]);
    }
    for (int idx = tid; idx < 1024; idx += 256)
        sM[(idx >> 5) * 33 + (idx & 31)] = d_M[idx];

    float nw1 = 0.f, nw2 = 0.f;
    if (tid < NG) { nw1 = d_NWv[tid * 3 + 1]; nw2 = d_NWv[tid * 3 + 2]; }

    {
        int k = tid >> 7, d = (tid >> 5) & 3, i = tid & 31;
        SA(0, k, d, i) = (d == 1) ? ((i == 1) ? 1.f : 0.f) : ((i == 0) ? ZO : 0.f);
        if (tid < 8) SP(0, tid >> 2, tid & 3) = ((tid & 3) == 1) ? 1.f : 0.f;
    }
    const float sh0 = sharp_in[0], sh1 = sharp_in[1];
    int buf = 0;
    __syncthreads();

    {
        float mypk = 0.f;
        if (tid < 64) {
            int k = tid >> 5, i = tid & 31;
            float s = 0.f;
#pragma unroll
            for (int d = 0; d < 4; d++) s += SP(buf, k, d) * SA(buf, k, d, i);
            ((float*)&sPk2[i])[k] = s;
            mypk = s;
        }
        __syncthreads();
        if (tid < 64) {
            int k = tid >> 5, i = tid & 31;
            float q = 0.f;
#pragma unroll
            for (int j = 0; j < 32; j++) q = fmaf(sM[i * 33 + j], ((float*)&sPk2[j])[k], q);
            float part = mypk * q;
            for (int o = 16; o; o >>= 1) part += __shfl_down_sync(0xffffffffu, part, o);
            if (i == 0) sNp[k] = sqrtf(fmaxf(part, 0.f));
        }
        __syncthreads();
    }

    float e0c = (tid < NG) ? d_E0[((size_t)0 * BB + b) * NG + tid] : 0.f;

    for (int t = 0; t < SS; t++) {
        float e0n = 0.f;
        if (tid < NG && t < SS - 1) e0n = d_E0[((size_t)(t + 1) * BB + b) * NG + tid];

        if (tid < 144) {
            float inv0 = 1.f / fmaxf(sNp[0], EPS);
            float inv1 = 1.f / fmaxf(sNp[1], EPS);
            float d1a = 0.f, d1b = 0.f, d2a = 0.f, d2b = 0.f;
#pragma unroll
            for (int i = 0; i < 32; i += 2) {
                float2 pa = sPk2[i];
                float2 ga = G12[i * 208 + tid];
                d1a = fmaf(pa.x, ga.x, d1a); d2a = fmaf(pa.y, ga.y, d2a);
                float2 pb = sPk2[i + 1];
                float2 gb = G12[(i + 1) * 208 + tid];
                d1b = fmaf(pb.x, gb.x, d1b); d2b = fmaf(pb.y, gb.y, d2b);
            }
            float c1 = fabsf(d1a + d1b) * inv0;
            float c2 = fabsf(d2a + d2b) * inv1;
            float t1 = nw1 * c1 + (1.f - nw1) * (1.f - c1);
            float t2 = nw2 * c2 + (1.f - nw2) * (1.f - c2);
            sG[tid] = e0c * t1 * t2;
        }
        __syncthreads();

        if (tid < 64) {
            int k = tid >> 5, cc = tid & 31;
            int base = 16 + (k << 6) + (cc << 1);
            float cf = sG[base] + sG[base + 1];
            float cf30 = __shfl_sync(0xffffffffu, cf, 30);
            float cf31 = __shfl_sync(0xffffffffu, cf, 31);
            float cfm2 = __shfl_up_sync(0xffffffffu, cf, 2);
            float2 pk = sPk2[cc];
            float v = cf30 * pk.x + cf31 * pk.y + ((cc >= 2) ? cfm2 : 0.f);
            sPv[k * 32 + cc] = v;
        } else if (tid < 66) {
            int k = tid - 64;
            float sh = k ? sh1 : sh0;
            float pp = fmaxf(sG[k * 4 + 0], sG[k * 4 + 1]) * sh;
            float pn = fmaxf(sG[k * 4 + 2], sG[k * 4 + 3]) * sh;
            float m = fmaxf(pp, pn);
            float ea = expf(pp - m), eb = expf(pn - m);
            sProb[k * 2 + 0] = ea / (ea + eb);
            float qp = fmaxf(sG[8 + k * 4 + 0], sG[8 + k * 4 + 1]) * sh;
            float qn = fmaxf(sG[8 + k * 4 + 2], sG[8 + k * 4 + 3]) * sh;
            float m2 = fmaxf(qp, qn);
            float ec = expf(qp - m2), ed = expf(qn - m2);
            sProb[k * 2 + 1] = ec / (ec + ed);
        }
        __syncthreads();

        {
            int k = tid >> 7, d = (tid >> 5) & 3, i = tid & 31;
            float a   = SA(buf, k, d, i);
            float pd  = SP(buf, k, d);
            float pdp = SP(buf, k, (d + 1) & 3);
            float pdm = SP(buf, k, (d - 1) & 3);
            float pop  = sProb[k * 2 + 0];
            float push = sProb[k * 2 + 1];
            float pv = sPv[k * 32 + i];
            float ps = a * (1.f - pd) + ((i == 0) ? ZO : 0.f) * pd;
            float s1 = ps * pop + a * (1.f - pop);
            float prold = pd * pop + pdm * (1.f - pop);
            float p1d   = pdp * pop + pd * (1.f - pop);
            float ps2 = s1 * (1.f - prold) + pv * prold;
            float s2 = ps2 * push + s1 * (1.f - push);
            float p2 = prold * push + p1d * (1.f - push);
            SA(buf ^ 1, k, d, i) = s2;
            if (i == 0) SP(buf ^ 1, k, d) = p2;
        }
        __syncthreads();
        buf ^= 1;

        float mypk = 0.f;
        if (tid < 64) {
            int k = tid >> 5, i = tid & 31;
            float s = 0.f;
#pragma unroll
            for (int d = 0; d < 4; d++) s += SP(buf, k, d) * SA(buf, k, d, i);
            ((float*)&sPk2[i])[k] = s;
            mypk = s;
        }
        __syncthreads();
        if (tid < 64) {
            int k = tid >> 5, i = tid & 31;
            float q = 0.f;
#pragma unroll
            for (int j = 0; j < 32; j++) q = fmaf(sM[i * 33 + j], ((float*)&sPk2[j])[k], q);
            float part = mypk * q;
            for (int o = 16; o; o >>= 1) part += __shfl_down_sync(0xffffffffu, part, o);
            if (i == 0) sNp[k] = sqrtf(fmaxf(part, 0.f));
        }
        __syncthreads();

        if (tid >= 144 && tid < NG) {
            float inv0 = 1.f / fmaxf(sNp[0], EPS);
            float inv1 = 1.f / fmaxf(sNp[1], EPS);
            float d1a = 0.f, d1b = 0.f, d2a = 0.f, d2b = 0.f;
#pragma unroll
            for (int i = 0; i < 32; i += 2) {
                float2 pa = sPk2[i];
                float2 ga = G12[i * 208 + tid];
                d1a = fmaf(pa.x, ga.x, d1a); d2a = fmaf(pa.y, ga.y, d2a);
                float2 pb = sPk2[i + 1];
                float2 gb = G12[(i + 1) * 208 + tid];
                d1b = fmaf(pb.x, gb.x, d1b); d2b = fmaf(pb.y, gb.y, d2b);
            }
            float c1 = fabsf(d1a + d1b) * inv0;
            float c2 = fabsf(d2a + d2b) * inv1;
            float t1 = nw1 * c1 + (1.f - nw1) * (1.f - c1);
            float t2 = nw2 * c2 + (1.f - nw2) * (1.f - c2);
            sG[tid] = e0c * t1 * t2;
        }
        __syncthreads();

        if (tid < 32) {
            int base = 144 + (tid << 1);
            float cf = sG[base] + sG[base + 1];
            float cf30 = __shfl_sync(0xffffffffu, cf, 30);
            float cf31 = __shfl_sync(0xffffffffu, cf, 31);
            float cfm2 = __shfl_up_sync(0xffffffffu, cf, 2);
            float2 pk = sPk2[tid];
            float v = cf30 * pk.x + cf31 * pk.y + ((tid >= 2) ? cfm2 : 0.f);
            d_OC[((size_t)b * SS + t) * 32 + tid] = v;
        }
        e0c = e0n;
    }
#undef SA
#undef SP
}

// ============================================================
// Output projection: out[r][v] = oc0 + oc1*siv[v] + sum_h oc[2+h]*syms[h][v]
// ============================================================
__global__ __launch_bounds__(256) void k_out(const float* __restrict__ siv,
                                             const float* __restrict__ syms,
                                             float* __restrict__ out) {
    __shared__ float sv[31][256];
    __shared__ float soc[64][32];
    int v0 = blockIdx.y * 256;
    int r0 = blockIdx.x * 64;
    int tid = threadIdx.x;
#pragma unroll
    for (int e = 0; e < 31; e++) {
        int idx = tid + e * 256;
        int h = idx >> 8, v = idx & 255;
        sv[h][v] = (h == 0) ? siv[v0 + v] : syms[(h - 1) * VDIM + v0 + v];
    }
#pragma unroll
    for (int e = 0; e < 8; e++) {
        int idx = tid + e * 256;
        soc[idx >> 5][idx & 31] = d_OC[(size_t)(r0 + (idx >> 5)) * 32 + (idx & 31)];
    }
    __syncthreads();
#pragma unroll 4
    for (int rr = 0; rr < 64; rr++) {
        float acc = soc[rr][0];
        acc += soc[rr][1] * sv[0][tid];
#pragma unroll
        for (int h = 0; h < 30; h++) acc += soc[rr][2 + h] * sv[1 + h][tid];
        out[(size_t)(r0 + rr) * VDIM + v0 + tid] = acc;
    }
}

// ============================================================
extern "C" void kernel_launch(void* const* d_in, const int* in_sizes, int n_in,
                              void* d_out, int out_size) {
    const float* x         = (const float*)d_in[0];
    const float* syms      = (const float*)d_in[1];
    const float* siv       = (const float*)d_in[2];
    const float* sharp     = (const float*)d_in[3];
    const float* pop_w     = (const float*)d_in[4];
    const float* pop_nw    = (const float*)d_in[5];
    const float* pushop_w  = (const float*)d_in[6];
    const float* pushop_nw = (const float*)d_in[7];
    const float* pushfn_w  = (const float*)d_in[8];
    const float* pushfn_nw = (const float*)d_in[9];
    const float* calc_w    = (const float*)d_in[10];
    const float* calc_nw   = (const float*)d_in[11];
    float* out = (float*)d_out;

    const int scan_smem = SCAN_SMEM_FLOATS * (int)sizeof(float);
    cudaFuncSetAttribute(k_scan, cudaFuncAttributeMaxDynamicSharedMemorySize, scan_smem);

    k_gram<<<dim3(32, 32), 32>>>(siv, syms);
    k_setup<<<NG, 256>>>(siv, syms, pop_w, pop_nw, pushop_w, pushop_nw,
                         pushfn_w, pushfn_nw, calc_w, calc_nw);
    k_xnorm<<<256, 256>>>(x);
    k_e0<<<256, 256>>>(x);
    k_scan<<<BB, 256, scan_smem>>>(sharp);
    k_out<<<dim3(512, 2), 256>>>(siv, syms, out);
}

// round 15
// speedup vs baseline: 1.9038x; 1.0416x over previous
#include <cuda_runtime.h>
#include <cuda_bf16.h>
#include <math.h>
#include <stdint.h>

// ---- problem constants ----
#define NG   208      // total gates: pop(8) + pushop(8) + pushfn(128) + calc(64)
#define VDIM 512
#define BB   256
#define SS   128
#define ZO   1e-6f
#define EPS  1e-8f

// ---- device scratch (no allocations allowed) ----
__device__ float d_M[32 * 32];                    // Gram of 32-dim basis
__device__ float d_Gn1[NG * 32];                  // basis . w_vec1 / max(||w_vec1||,eps)
__device__ float d_Gn2[NG * 32];                  // basis . w_vec2 / max(||w_vec2||,eps)
__device__ float d_NWv[NG * 3];                   // sigmoid(nw_raw)
__device__ __nv_bfloat16 d_BThi[(size_t)VDIM * NG]; // normalized w0 hi bf16, TRANSPOSED [v][c]
__device__ __nv_bfloat16 d_BTlo[(size_t)VDIM * NG]; // residual lo bf16, TRANSPOSED [v][c]
__device__ float d_invnx[BB * SS];                // 1/max(||x_row||,eps)
__device__ float d_E0[(size_t)SS * BB * NG];      // precomputed vec0 interp term
__device__ float d_OC[(size_t)BB * SS * 32];      // output coefficients

// ---- warp-MMA helpers (baseline ISA: sm_80+, compiles for plain sm_103) ----
__device__ __forceinline__ uint32_t smem_u32(const void* p) {
    uint32_t a;
    asm("{ .reg .u64 t; cvta.to.shared.u64 t, %1; cvt.u32.u64 %0, t; }" : "=r"(a) : "l"(p));
    return a;
}
__device__ __forceinline__ void ldsm4(uint32_t* a, uint32_t addr) {
    asm volatile("ldmatrix.sync.aligned.m8n8.x4.shared.b16 {%0,%1,%2,%3}, [%4];"
        : "=r"(a[0]), "=r"(a[1]), "=r"(a[2]), "=r"(a[3]) : "r"(addr));
}
__device__ __forceinline__ void ldsm2t(uint32_t* b, uint32_t addr) {
    asm volatile("ldmatrix.sync.aligned.m8n8.x2.trans.shared.b16 {%0,%1}, [%2];"
        : "=r"(b[0]), "=r"(b[1]) : "r"(addr));
}
__device__ __forceinline__ void mma_bf16(float* d, const uint32_t* a, const uint32_t* b) {
    asm volatile("mma.sync.aligned.m16n8k16.row.col.f32.bf16.bf16.f32 "
        "{%0,%1,%2,%3}, {%4,%5,%6,%7}, {%8,%9}, {%0,%1,%2,%3};"
        : "+f"(d[0]), "+f"(d[1]), "+f"(d[2]), "+f"(d[3])
        : "r"(a[0]), "r"(a[1]), "r"(a[2]), "r"(a[3]), "r"(b[0]), "r"(b[1]));
}

// ============================================================
// Gram matrix of the 32-dim basis: b0 = ones, b1 = siv, b2+h = syms[h]
// ============================================================
__global__ void k_gram(const float* __restrict__ siv, const float* __restrict__ syms) {
    int i = blockIdx.x, j = blockIdx.y;
    int lane = threadIdx.x;
    float s = 0.f;
    for (int v = lane; v < VDIM; v += 32) {
        float bi = (i == 0) ? 1.f : ((i == 1) ? siv[v] : syms[(i - 2) * VDIM + v]);
        float bj = (j == 0) ? 1.f : ((j == 1) ? siv[v] : syms[(j - 2) * VDIM + v]);
        s += bi * bj;
    }
    for (int o = 16; o; o >>= 1) s += __shfl_down_sync(0xffffffffu, s, o);
    if (lane == 0) d_M[i * 32 + j] = s;
}

// ============================================================
// Per-gate preprocessing (emits TRANSPOSED bf16 hi/lo split of normalized w0)
// ============================================================
__global__ void k_setup(const float* __restrict__ siv, const float* __restrict__ syms,
                        const float* __restrict__ pop_w, const float* __restrict__ pop_nw,
                        const float* __restrict__ pushop_w, const float* __restrict__ pushop_nw,
                        const float* __restrict__ pushfn_w, const float* __restrict__ pushfn_nw,
                        const float* __restrict__ calc_w, const float* __restrict__ calc_nw) {
    int c = blockIdx.x;
    const float* wb;
    const float* nb;
    if (c < 8)        { wb = pop_w    + (size_t)c * 3 * VDIM;          nb = pop_nw    + (size_t)c * 3; }
    else if (c < 16)  { wb = pushop_w + (size_t)(c - 8) * 3 * VDIM;    nb = pushop_nw + (size_t)(c - 8) * 3; }
    else if (c < 144) { wb = pushfn_w + (size_t)(c - 16) * 3 * VDIM;   nb = pushfn_nw + (size_t)(c - 16) * 3; }
    else              { wb = calc_w   + (size_t)(c - 144) * 3 * VDIM;  nb = calc_nw   + (size_t)(c - 144) * 3; }

    __shared__ float sg[67];
    int warp = threadIdx.x >> 5, lane = threadIdx.x & 31;
    for (int job = warp; job < 67; job += 8) {
        const float* w;
        int bi;
        if (job < 64) { bi = job >> 1; w = wb + ((job & 1) + 1) * VDIM; }
        else          { bi = -1;       w = wb + (job - 64) * VDIM; }
        float s = 0.f;
        for (int v = lane; v < VDIM; v += 32) {
            float wv = w[v];
            float bv = (bi < 0) ? wv
                     : ((bi == 0) ? 1.f : ((bi == 1) ? siv[v] : syms[(bi - 2) * VDIM + v]));
            s += wv * bv;
        }
        for (int o = 16; o; o >>= 1) s += __shfl_down_sync(0xffffffffu, s, o);
        if (!lane) sg[job] = s;
    }
    __syncthreads();
    if (threadIdx.x < 64) {
        int bi = threadIdx.x >> 1, vecsel = threadIdx.x & 1;
        float n = fmaxf(sqrtf(sg[65 + vecsel]), EPS);
        float g = sg[threadIdx.x] / n;
        if (vecsel == 0) d_Gn1[c * 32 + bi] = g;
        else             d_Gn2[c * 32 + bi] = g;
    }
    if (threadIdx.x < 3) d_NWv[c * 3 + threadIdx.x] = 1.f / (1.f + expf(-nb[threadIdx.x]));
    float n0 = fmaxf(sqrtf(sg[64]), EPS);
    for (int v = threadIdx.x; v < VDIM; v += blockDim.x) {
        float val = wb[v] / n0;
        __nv_bfloat16 h = __float2bfloat16(val);
        d_BThi[(size_t)v * NG + c] = h;
        d_BTlo[(size_t)v * NG + c] = __float2bfloat16(val - __bfloat162float(h));
    }
}

// ============================================================
// Row norms of x: one warp per row
// ============================================================
__global__ void k_xnorm(const float* __restrict__ x) {
    int wg = (blockIdx.x * blockDim.x + threadIdx.x) >> 5;
    int lane = threadIdx.x & 31;
    int nwarps = (gridDim.x * blockDim.x) >> 5;
    for (int r = wg; r < BB * SS; r += nwarps) {
        const float* xr = x + (size_t)r * VDIM;
        float s = 0.f;
        for (int v = lane; v < VDIM; v += 32) { float t = xr[v]; s += t * t; }
        for (int o = 16; o; o >>= 1) s += __shfl_down_sync(0xffffffffu, s, o);
        if (!lane) d_invnx[r] = 1.f / fmaxf(sqrtf(s), EPS);
    }
}

// ============================================================
// E0 GEMM via mma.sync bf16 hi/lo split (fp32 acc) — unchanged R14-passing.
// ============================================================
__global__ __launch_bounds__(256) void k_e0(const float* __restrict__ x) {
    __shared__ __align__(16) __nv_bfloat16 As_hi[128 * 40];
    __shared__ __align__(16) __nv_bfloat16 As_lo[128 * 40];
    __shared__ __align__(16) __nv_bfloat16 Bs_hi[32 * 216];
    __shared__ __align__(16) __nv_bfloat16 Bs_lo[32 * 216];

    const int tid = threadIdx.x;
    const int wid = tid >> 5, lane = tid & 31;
    const int m0 = blockIdx.x * 128;

    const uint32_t uAh = smem_u32(As_hi), uAl = smem_u32(As_lo);
    const uint32_t uBh = smem_u32(Bs_hi), uBl = smem_u32(Bs_lo);

    float acc[26][4];
#pragma unroll
    for (int nt = 0; nt < 26; nt++)
#pragma unroll
        for (int q = 0; q < 4; q++) acc[nt][q] = 0.f;

    const int ar = tid >> 1, aq = tid & 1;
    const int am = m0 + ar;
    const float* xrow = x + ((size_t)((am & 255) * SS + (am >> 8))) * VDIM + aq * 16;

    for (int ch = 0; ch < 16; ch++) {
        const int k0 = ch * 32;
        __syncthreads();
        {
            uint32_t* hrow = (uint32_t*)(As_hi + ar * 40 + aq * 16);
            uint32_t* lrow = (uint32_t*)(As_lo + ar * 40 + aq * 16);
#pragma unroll
            for (int i = 0; i < 4; i++) {
                float4 v = *(const float4*)(xrow + k0 + i * 4);
                __nv_bfloat16 h0 = __float2bfloat16(v.x);
                __nv_bfloat16 h1 = __float2bfloat16(v.y);
                __nv_bfloat16 h2 = __float2bfloat16(v.z);
                __nv_bfloat16 h3 = __float2bfloat16(v.w);
                __nv_bfloat16 l0 = __float2bfloat16(v.x - __bfloat162float(h0));
                __nv_bfloat16 l1 = __float2bfloat16(v.y - __bfloat162float(h1));
                __nv_bfloat16 l2 = __float2bfloat16(v.z - __bfloat162float(h2));
                __nv_bfloat16 l3 = __float2bfloat16(v.w - __bfloat162float(h3));
                hrow[i * 2 + 0] = (uint32_t)__bfloat16_as_ushort(h0) | ((uint32_t)__bfloat16_as_ushort(h1) << 16);
                hrow[i * 2 + 1] = (uint32_t)__bfloat16_as_ushort(h2) | ((uint32_t)__bfloat16_as_ushort(h3) << 16);
                lrow[i * 2 + 0] = (uint32_t)__bfloat16_as_ushort(l0) | ((uint32_t)__bfloat16_as_ushort(l1) << 16);
                lrow[i * 2 + 1] = (uint32_t)__bfloat16_as_ushort(l2) | ((uint32_t)__bfloat16_as_ushort(l3) << 16);
            }
        }
        {
            const uint32_t* bhr = (const uint32_t*)d_BThi;   // [512][104] u32
            const uint32_t* blr = (const uint32_t*)d_BTlo;
            uint32_t* bsh = (uint32_t*)Bs_hi;                // [32][108] u32
            uint32_t* bsl = (uint32_t*)Bs_lo;
#pragma unroll
            for (int i = 0; i < 13; i++) {
                int idx = tid + i * 256;                     // < 3328
                int kk = idx / 104, j = idx - kk * 104;
                bsh[kk * 108 + j] = bhr[(size_t)(k0 + kk) * 104 + j];
                bsl[kk * 108 + j] = blr[(size_t)(k0 + kk) * 104 + j];
            }
        }
        __syncthreads();
#pragma unroll
        for (int ksub = 0; ksub < 32; ksub += 16) {
            uint32_t ah[4], al[4];
            uint32_t aoff = ((uint32_t)((wid * 16 + (lane & 15)) * 40 + ksub + ((lane >> 4) << 3))) * 2;
            ldsm4(ah, uAh + aoff);
            ldsm4(al, uAl + aoff);
            uint32_t brow = ((uint32_t)((ksub + (lane & 15)) * 216)) * 2;
#pragma unroll
            for (int nt = 0; nt < 26; nt++) {
                uint32_t bh[2], bl[2];
                uint32_t boff = brow + nt * 16;
                ldsm2t(bh, uBh + boff);
                ldsm2t(bl, uBl + boff);
                mma_bf16(acc[nt], ah, bh);
                mma_bf16(acc[nt], ah, bl);
                mma_bf16(acc[nt], al, bh);
            }
        }
    }

    const int mA = m0 + wid * 16 + (lane >> 2);
    const int mB = mA + 8;
    const float inxA = d_invnx[(mA & 255) * SS + (mA >> 8)];
    const float inxB = d_invnx[(mB & 255) * SS + (mB >> 8)];
    float* eA = &d_E0[(size_t)mA * NG];
    float* eB = &d_E0[(size_t)mB * NG];
    const int c0 = (lane & 3) * 2;
#pragma unroll
    for (int nt = 0; nt < 26; nt++) {
        int c = nt * 8 + c0;
        float nw0 = d_NWv[c * 3];
        float nw1 = d_NWv[(c + 1) * 3];
        float a0 = fabsf(acc[nt][0] * inxA);
        float a1 = fabsf(acc[nt][1] * inxA);
        float b0 = fabsf(acc[nt][2] * inxB);
        float b1 = fabsf(acc[nt][3] * inxB);
        eA[c]     = nw0 * a0 + (1.f - nw0) * (1.f - a0);
        eA[c + 1] = nw1 * a1 + (1.f - nw1) * (1.f - a1);
        eB[c]     = nw0 * b0 + (1.f - nw0) * (1.f - b0);
        eB[c + 1] = nw1 * b1 + (1.f - nw1) * (1.f - b1);
    }
}

// ============================================================
// Sequential scan, v2: 2 batch lanes per block (128 blocks x 512 thr, one wave),
// gate weights REGISTER-resident, peek-norm via shfl, 5 NAMED barriers/step
// (per-lane bar.sync so the two lanes never wait on each other).
// ============================================================
__global__ __launch_bounds__(512, 1) void k_scan(const float* __restrict__ sharp_in) {
    __shared__ float sM[32 * 33];                 // padded Gram (shared by lanes)
    __shared__ float sAa[2][2][2][4][32];         // [ln][buf][k][d][i]
    __shared__ float sPp[2][2][2][4];             // [ln][buf][k][d]
    __shared__ float2 sPk2[2][32];                // [ln][i] = (pk0_i, pk1_i)
    __shared__ float sNp[2][2];                   // [ln][k]
    __shared__ float sG[2][NG];                   // [ln][gate]
    __shared__ float sPv[2][2][32];               // [ln][k][i]
    __shared__ float sProb[2][4];                 // [ln][k*2 + {pop,push}]

    const int tid = threadIdx.x;
    const int ln  = tid >> 8;                     // lane 0/1
    const int lid = tid & 255;                    // position within lane
    const int b   = blockIdx.x * 2 + ln;
    const int barid = ln + 1;

#define LBAR() asm volatile("bar.sync %0, 256;" :: "r"(barid) : "memory")

    // ---- register-resident gate weights ----
    float rG1[32], rG2[32];
    float nw1 = 0.f, nw2 = 0.f;
    if (lid < NG) {
#pragma unroll
        for (int i = 0; i < 32; i++) {
            rG1[i] = d_Gn1[lid * 32 + i];
            rG2[i] = d_Gn2[lid * 32 + i];
        }
        nw1 = d_NWv[lid * 3 + 1];
        nw2 = d_NWv[lid * 3 + 2];
    }
    for (int idx = tid; idx < 1024; idx += 512)
        sM[(idx >> 5) * 33 + (idx & 31)] = d_M[idx];

    // ---- init stacks (buf 0): slots ZO*ones, slot1 = siv (hard push), ptr@1 ----
    {
        int k = lid >> 7, d = (lid >> 5) & 3, i = lid & 31;
        sAa[ln][0][k][d][i] = (d == 1) ? ((i == 1) ? 1.f : 0.f) : ((i == 0) ? ZO : 0.f);
        if (lid < 8) sPp[ln][0][lid >> 2][lid & 3] = ((lid & 3) == 1) ? 1.f : 0.f;
    }
    const float sh0 = sharp_in[0], sh1 = sharp_in[1];
    int buf = 0;
    __syncthreads();

    // ---- initial peek + norm (shfl-based) ----
    if (lid < 64) {
        int k = lid >> 5, i = lid & 31;
        float mypk = 0.f;
#pragma unroll
        for (int d = 0; d < 4; d++) mypk += sPp[ln][buf][k][d] * sAa[ln][buf][k][d][i];
        ((float*)&sPk2[ln][i])[k] = mypk;
        float q = 0.f;
#pragma unroll
        for (int j = 0; j < 32; j++)
            q = fmaf(sM[i * 33 + j], __shfl_sync(0xffffffffu, mypk, j), q);
        float part = mypk * q;
        for (int o = 16; o; o >>= 1) part += __shfl_down_sync(0xffffffffu, part, o);
        if (i == 0) sNp[ln][k] = sqrtf(fmaxf(part, 0.f));
    }
    LBAR();

    float e0c = (lid < NG) ? d_E0[((size_t)0 * BB + b) * NG + lid] : 0.f;

    for (int t = 0; t < SS; t++) {
        float e0n = 0.f;
        if (lid < NG && t < SS - 1) e0n = d_E0[((size_t)(t + 1) * BB + b) * NG + lid];

        // ---- phase A gates (lid < 144), G in registers, sPk2 broadcast ----
        if (lid < 144) {
            float inv0 = 1.f / fmaxf(sNp[ln][0], EPS);
            float inv1 = 1.f / fmaxf(sNp[ln][1], EPS);
            float d1 = 0.f, d2 = 0.f;
#pragma unroll
            for (int i = 0; i < 32; i++) {
                float2 p = sPk2[ln][i];
                d1 = fmaf(p.x, rG1[i], d1);
                d2 = fmaf(p.y, rG2[i], d2);
            }
            float c1 = fabsf(d1) * inv0;
            float c2 = fabsf(d2) * inv1;
            float t1 = nw1 * c1 + (1.f - nw1) * (1.f - c1);
            float t2 = nw2 * c2 + (1.f - nw2) * (1.f - c2);
            sG[ln][lid] = e0c * t1 * t2;
        }
        LBAR();                                   // bar1: sG[0..143] ready

        // ---- push coefs + push value (lid<64 via shfl); probs (lid 64,65) ----
        if (lid < 64) {
            int k = lid >> 5, cc = lid & 31;
            int base = 16 + (k << 6) + (cc << 1);
            float cf = sG[ln][base] + sG[ln][base + 1];
            float cf30 = __shfl_sync(0xffffffffu, cf, 30);
            float cf31 = __shfl_sync(0xffffffffu, cf, 31);
            float cfm2 = __shfl_up_sync(0xffffffffu, cf, 2);
            float2 pk = sPk2[ln][cc];
            float v = cf30 * pk.x + cf31 * pk.y + ((cc >= 2) ? cfm2 : 0.f);
            sPv[ln][k][cc] = v;
        } else if (lid < 66) {
            int k = lid - 64;
            float sh = k ? sh1 : sh0;
            float pp = fmaxf(sG[ln][k * 4 + 0], sG[ln][k * 4 + 1]) * sh;
            float pn = fmaxf(sG[ln][k * 4 + 2], sG[ln][k * 4 + 3]) * sh;
            float m = fmaxf(pp, pn);
            float ea = expf(pp - m), eb = expf(pn - m);
            sProb[ln][k * 2 + 0] = ea / (ea + eb);
            float qp = fmaxf(sG[ln][8 + k * 4 + 0], sG[ln][8 + k * 4 + 1]) * sh;
            float qn = fmaxf(sG[ln][8 + k * 4 + 2], sG[ln][8 + k * 4 + 3]) * sh;
            float m2 = fmaxf(qp, qn);
            float ec = expf(qp - m2), ed = expf(qn - m2);
            sProb[ln][k * 2 + 1] = ec / (ec + ed);
        }
        LBAR();                                   // bar2: sPv, sProb ready

        // ---- stack update: pop_or_nop then push_or_nop, double-buffered ----
        {
            int k = lid >> 7, d = (lid >> 5) & 3, i = lid & 31;
            float a   = sAa[ln][buf][k][d][i];
            float pd  = sPp[ln][buf][k][d];
            float pdp = sPp[ln][buf][k][(d + 1) & 3];
            float pdm = sPp[ln][buf][k][(d - 1) & 3];
            float pop  = sProb[ln][k * 2 + 0];
            float push = sProb[ln][k * 2 + 1];
            float pv = sPv[ln][k][i];
            float ps = a * (1.f - pd) + ((i == 0) ? ZO : 0.f) * pd;
            float s1 = ps * pop + a * (1.f - pop);
            float prold = pd * pop + pdm * (1.f - pop);   // roll(p_after_pop,+1)[d]
            float p1d   = pdp * pop + pd * (1.f - pop);   // p_after_pop[d]
            float ps2 = s1 * (1.f - prold) + pv * prold;
            float s2 = ps2 * push + s1 * (1.f - push);
            float p2 = prold * push + p1d * (1.f - push);
            sAa[ln][buf ^ 1][k][d][i] = s2;
            if (i == 0) sPp[ln][buf ^ 1][k][d] = p2;
        }
        LBAR();                                   // bar3: new stacks ready
        buf ^= 1;

        // ---- new peeks + norms (shfl, merged barrier) ----
        if (lid < 64) {
            int k = lid >> 5, i = lid & 31;
            float mypk = 0.f;
#pragma unroll
            for (int d = 0; d < 4; d++) mypk += sPp[ln][buf][k][d] * sAa[ln][buf][k][d][i];
            ((float*)&sPk2[ln][i])[k] = mypk;
            float q = 0.f;
#pragma unroll
            for (int j = 0; j < 32; j++)
                q = fmaf(sM[i * 33 + j], __shfl_sync(0xffffffffu, mypk, j), q);
            float part = mypk * q;
            for (int o = 16; o; o >>= 1) part += __shfl_down_sync(0xffffffffu, part, o);
            if (i == 0) sNp[ln][k] = sqrtf(fmaxf(part, 0.f));
        }
        LBAR();                                   // bar4: sPk2 + sNp ready

        // ---- phase B: calc gates (lid 144..207) with new peeks ----
        if (lid >= 144 && lid < NG) {
            float inv0 = 1.f / fmaxf(sNp[ln][0], EPS);
            float inv1 = 1.f / fmaxf(sNp[ln][1], EPS);
            float d1 = 0.f, d2 = 0.f;
#pragma unroll
            for (int i = 0; i < 32; i++) {
                float2 p = sPk2[ln][i];
                d1 = fmaf(p.x, rG1[i], d1);
                d2 = fmaf(p.y, rG2[i], d2);
            }
            float c1 = fabsf(d1) * inv0;
            float c2 = fabsf(d2) * inv1;
            float t1 = nw1 * c1 + (1.f - nw1) * (1.f - c1);
            float t2 = nw2 * c2 + (1.f - nw2) * (1.f - c2);
            sG[ln][lid] = e0c * t1 * t2;
        }
        LBAR();                                   // bar5: sG[144..207] ready

        // ---- output coefficients (lid < 32 via shfl) ----
        if (lid < 32) {
            int base = 144 + (lid << 1);
            float cf = sG[ln][base] + sG[ln][base + 1];
            float cf30 = __shfl_sync(0xffffffffu, cf, 30);
            float cf31 = __shfl_sync(0xffffffffu, cf, 31);
            float cfm2 = __shfl_up_sync(0xffffffffu, cf, 2);
            float2 pk = sPk2[ln][lid];
            float v = cf30 * pk.x + cf31 * pk.y + ((lid >= 2) ? cfm2 : 0.f);
            d_OC[((size_t)b * SS + t) * 32 + lid] = v;
        }
        e0c = e0n;
    }
#undef LBAR
}

// ============================================================
// Output projection: out[r][v] = oc0 + oc1*siv[v] + sum_h oc[2+h]*syms[h][v]
// ============================================================
__global__ __launch_bounds__(256) void k_out(const float* __restrict__ siv,
                                             const float* __restrict__ syms,
                                             float* __restrict__ out) {
    __shared__ float sv[31][256];
    __shared__ float soc[64][32];
    int v0 = blockIdx.y * 256;
    int r0 = blockIdx.x * 64;
    int tid = threadIdx.x;
#pragma unroll
    for (int e = 0; e < 31; e++) {
        int idx = tid + e * 256;
        int h = idx >> 8, v = idx & 255;
        sv[h][v] = (h == 0) ? siv[v0 + v] : syms[(h - 1) * VDIM + v0 + v];
    }
#pragma unroll
    for (int e = 0; e < 8; e++) {
        int idx = tid + e * 256;
        soc[idx >> 5][idx & 31] = d_OC[(size_t)(r0 + (idx >> 5)) * 32 + (idx & 31)];
    }
    __syncthreads();
#pragma unroll 4
    for (int rr = 0; rr < 64; rr++) {
        float acc = soc[rr][0];
        acc += soc[rr][1] * sv[0][tid];
#pragma unroll
        for (int h = 0; h < 30; h++) acc += soc[rr][2 + h] * sv[1 + h][tid];
        out[(size_t)(r0 + rr) * VDIM + v0 + tid] = acc;
    }
}

// ============================================================
extern "C" void kernel_launch(void* const* d_in, const int* in_sizes, int n_in,
                              void* d_out, int out_size) {
    const float* x         = (const float*)d_in[0];
    const float* syms      = (const float*)d_in[1];
    const float* siv       = (const float*)d_in[2];
    const float* sharp     = (const float*)d_in[3];
    const float* pop_w     = (const float*)d_in[4];
    const float* pop_nw    = (const float*)d_in[5];
    const float* pushop_w  = (const float*)d_in[6];
    const float* pushop_nw = (const float*)d_in[7];
    const float* pushfn_w  = (const float*)d_in[8];
    const float* pushfn_nw = (const float*)d_in[9];
    const float* calc_w    = (const float*)d_in[10];
    const float* calc_nw   = (const float*)d_in[11];
    float* out = (float*)d_out;

    k_gram<<<dim3(32, 32), 32>>>(siv, syms);
    k_setup<<<NG, 256>>>(siv, syms, pop_w, pop_nw, pushop_w, pushop_nw,
                         pushfn_w, pushfn_nw, calc_w, calc_nw);
    k_xnorm<<<256, 256>>>(x);
    k_e0<<<256, 256>>>(x);
    k_scan<<<BB / 2, 512>>>(sharp);
    k_out<<<dim3(512, 2), 256>>>(siv, syms, out);
}

// round 16
// speedup vs baseline: 2.1922x; 1.1515x over previous
#include <cuda_runtime.h>
#include <cuda_bf16.h>
#include <math.h>
#include <stdint.h>

// ---- problem constants ----
#define NG   208      // total gates: pop(8) + pushop(8) + pushfn(128) + calc(64)
#define VDIM 512
#define BB   256
#define SS   128
#define ZO   1e-6f
#define EPS  1e-8f

// ---- device scratch (no allocations allowed) ----
__device__ float d_M[32 * 32];                    // Gram of 32-dim basis
__device__ float d_Gn1[NG * 32];                  // basis . w_vec1 / max(||w_vec1||,eps)
__device__ float d_Gn2[NG * 32];                  // basis . w_vec2 / max(||w_vec2||,eps)
__device__ float d_NWv[NG * 3];                   // sigmoid(nw_raw)
__device__ __nv_bfloat16 d_Bcv_hi[(size_t)NG * VDIM]; // normalized w0 hi bf16 [c][v]
__device__ __nv_bfloat16 d_Bcv_lo[(size_t)NG * VDIM]; // residual lo bf16 [c][v]
__device__ __nv_bfloat16 d_BThi[(size_t)VDIM * NG];   // transposed [v][c]
__device__ __nv_bfloat16 d_BTlo[(size_t)VDIM * NG];   // transposed [v][c]
__device__ float d_E0[(size_t)SS * BB * NG];      // precomputed vec0 interp term
__device__ float d_OC[(size_t)BB * SS * 32];      // output coefficients

// ---- warp-MMA helpers (baseline ISA) ----
__device__ __forceinline__ uint32_t smem_u32(const void* p) {
    uint32_t a;
    asm("{ .reg .u64 t; cvta.to.shared.u64 t, %1; cvt.u32.u64 %0, t; }" : "=r"(a) : "l"(p));
    return a;
}
__device__ __forceinline__ void ldsm4(uint32_t* a, uint32_t addr) {
    asm volatile("ldmatrix.sync.aligned.m8n8.x4.shared.b16 {%0,%1,%2,%3}, [%4];"
        : "=r"(a[0]), "=r"(a[1]), "=r"(a[2]), "=r"(a[3]) : "r"(addr));
}
__device__ __forceinline__ void ldsm2t(uint32_t* b, uint32_t addr) {
    asm volatile("ldmatrix.sync.aligned.m8n8.x2.trans.shared.b16 {%0,%1}, [%2];"
        : "=r"(b[0]), "=r"(b[1]) : "r"(addr));
}
__device__ __forceinline__ void mma_bf16(float* d, const uint32_t* a, const uint32_t* b) {
    asm volatile("mma.sync.aligned.m16n8k16.row.col.f32.bf16.bf16.f32 "
        "{%0,%1,%2,%3}, {%4,%5,%6,%7}, {%8,%9}, {%0,%1,%2,%3};"
        : "+f"(d[0]), "+f"(d[1]), "+f"(d[2]), "+f"(d[3])
        : "r"(a[0]), "r"(a[1]), "r"(a[2]), "r"(a[3]), "r"(b[0]), "r"(b[1]));
}

// ============================================================
// Gram matrix of the 32-dim basis
// ============================================================
__global__ void k_gram(const float* __restrict__ siv, const float* __restrict__ syms) {
    int i = blockIdx.x, j = blockIdx.y;
    int lane = threadIdx.x;
    float s = 0.f;
    for (int v = lane; v < VDIM; v += 32) {
        float bi = (i == 0) ? 1.f : ((i == 1) ? siv[v] : syms[(i - 2) * VDIM + v]);
        float bj = (j == 0) ? 1.f : ((j == 1) ? siv[v] : syms[(j - 2) * VDIM + v]);
        s += bi * bj;
    }
    for (int o = 16; o; o >>= 1) s += __shfl_down_sync(0xffffffffu, s, o);
    if (lane == 0) d_M[i * 32 + j] = s;
}

// ============================================================
// Per-gate preprocessing (bf16 hi/lo split stored [c][v] COALESCED)
// ============================================================
__global__ void k_setup(const float* __restrict__ siv, const float* __restrict__ syms,
                        const float* __restrict__ pop_w, const float* __restrict__ pop_nw,
                        const float* __restrict__ pushop_w, const float* __restrict__ pushop_nw,
                        const float* __restrict__ pushfn_w, const float* __restrict__ pushfn_nw,
                        const float* __restrict__ calc_w, const float* __restrict__ calc_nw) {
    int c = blockIdx.x;
    const float* wb;
    const float* nb;
    if (c < 8)        { wb = pop_w    + (size_t)c * 3 * VDIM;          nb = pop_nw    + (size_t)c * 3; }
    else if (c < 16)  { wb = pushop_w + (size_t)(c - 8) * 3 * VDIM;    nb = pushop_nw + (size_t)(c - 8) * 3; }
    else if (c < 144) { wb = pushfn_w + (size_t)(c - 16) * 3 * VDIM;   nb = pushfn_nw + (size_t)(c - 16) * 3; }
    else              { wb = calc_w   + (size_t)(c - 144) * 3 * VDIM;  nb = calc_nw   + (size_t)(c - 144) * 3; }

    __shared__ float sg[67];
    int warp = threadIdx.x >> 5, lane = threadIdx.x & 31;
    for (int job = warp; job < 67; job += 8) {
        const float* w;
        int bi;
        if (job < 64) { bi = job >> 1; w = wb + ((job & 1) + 1) * VDIM; }
        else          { bi = -1;       w = wb + (job - 64) * VDIM; }
        float s = 0.f;
        for (int v = lane; v < VDIM; v += 32) {
            float wv = w[v];
            float bv = (bi < 0) ? wv
                     : ((bi == 0) ? 1.f : ((bi == 1) ? siv[v] : syms[(bi - 2) * VDIM + v]));
            s += wv * bv;
        }
        for (int o = 16; o; o >>= 1) s += __shfl_down_sync(0xffffffffu, s, o);
        if (!lane) sg[job] = s;
    }
    __syncthreads();
    if (threadIdx.x < 64) {
        int bi = threadIdx.x >> 1, vecsel = threadIdx.x & 1;
        float n = fmaxf(sqrtf(sg[65 + vecsel]), EPS);
        float g = sg[threadIdx.x] / n;
        if (vecsel == 0) d_Gn1[c * 32 + bi] = g;
        else             d_Gn2[c * 32 + bi] = g;
    }
    if (threadIdx.x < 3) d_NWv[c * 3 + threadIdx.x] = 1.f / (1.f + expf(-nb[threadIdx.x]));
    float n0 = fmaxf(sqrtf(sg[64]), EPS);
    for (int v = threadIdx.x; v < VDIM; v += blockDim.x) {
        float val = wb[v] / n0;
        __nv_bfloat16 h = __float2bfloat16(val);
        d_Bcv_hi[(size_t)c * VDIM + v] = h;
        d_Bcv_lo[(size_t)c * VDIM + v] = __float2bfloat16(val - __bfloat162float(h));
    }
}

// ============================================================
// Tiled transpose [c][v] -> [v][c] for both hi and lo (coalesced both sides)
// grid (16, 7), block (32, 8)
// ============================================================
__global__ void k_tr() {
    __shared__ __nv_bfloat16 th[32][33], tl[32][33];
    int v0 = blockIdx.x * 32, c0 = blockIdx.y * 32;
    int tx = threadIdx.x, ty = threadIdx.y;
#pragma unroll
    for (int r = 0; r < 4; r++) {
        int c = c0 + ty + r * 8;
        if (c < NG) {
            th[ty + r * 8][tx] = d_Bcv_hi[(size_t)c * VDIM + v0 + tx];
            tl[ty + r * 8][tx] = d_Bcv_lo[(size_t)c * VDIM + v0 + tx];
        }
    }
    __syncthreads();
#pragma unroll
    for (int r = 0; r < 4; r++) {
        int v = v0 + ty + r * 8;
        int c = c0 + tx;
        if (c < NG) {
            d_BThi[(size_t)v * NG + c] = th[tx][ty + r * 8];
            d_BTlo[(size_t)v * NG + c] = tl[tx][ty + r * 8];
        }
    }
}

// ============================================================
// E0 GEMM v3: mma.sync bf16 hi/lo split, 2 CTAs/SM.
// 512 blocks x 256 thr, M=64/block, 8 warps = 4 m-strips x 2 N-halves,
// acc[13][4] (52 regs). Row norms fused in (no separate xnorm kernel).
// ============================================================
__global__ __launch_bounds__(256, 2) void k_e0(const float* __restrict__ x) {
    __shared__ __align__(16) __nv_bfloat16 As_hi[64 * 40];
    __shared__ __align__(16) __nv_bfloat16 As_lo[64 * 40];
    __shared__ __align__(16) __nv_bfloat16 Bs_hi[32 * 216];
    __shared__ __align__(16) __nv_bfloat16 Bs_lo[32 * 216];
    __shared__ float sInv[64];

    const int tid = threadIdx.x;
    const int wid = tid >> 5, lane = tid & 31;
    const int ms = wid & 3, nh = wid >> 2;        // m-strip, n-half
    const int m0 = blockIdx.x * 64;

    const uint32_t uAh = smem_u32(As_hi), uAl = smem_u32(As_lo);
    const uint32_t uBh = smem_u32(Bs_hi), uBl = smem_u32(Bs_lo);

    float acc[13][4];
#pragma unroll
    for (int nt = 0; nt < 13; nt++)
#pragma unroll
        for (int q = 0; q < 4; q++) acc[nt][q] = 0.f;

    // A staging coords: 4 threads per row, 8 floats (2 float4) each
    const int ar = tid >> 2, aq = tid & 3;
    const int am = m0 + ar;
    const float* xrow = x + ((size_t)((am & 255) * SS + (am >> 8))) * VDIM + aq * 8;
    float sumsq = 0.f;

    for (int ch = 0; ch < 16; ch++) {
        const int k0 = ch * 32;
        __syncthreads();
        // ---- stage A: fp32 -> bf16 hi/lo (+ row-norm accumulation) ----
        {
            uint32_t* hrow = (uint32_t*)(As_hi + ar * 40 + aq * 8);
            uint32_t* lrow = (uint32_t*)(As_lo + ar * 40 + aq * 8);
#pragma unroll
            for (int i = 0; i < 2; i++) {
                float4 v = *(const float4*)(xrow + k0 + i * 4);
                sumsq += v.x * v.x + v.y * v.y + v.z * v.z + v.w * v.w;
                __nv_bfloat16 h0 = __float2bfloat16(v.x);
                __nv_bfloat16 h1 = __float2bfloat16(v.y);
                __nv_bfloat16 h2 = __float2bfloat16(v.z);
                __nv_bfloat16 h3 = __float2bfloat16(v.w);
                __nv_bfloat16 l0 = __float2bfloat16(v.x - __bfloat162float(h0));
                __nv_bfloat16 l1 = __float2bfloat16(v.y - __bfloat162float(h1));
                __nv_bfloat16 l2 = __float2bfloat16(v.z - __bfloat162float(h2));
                __nv_bfloat16 l3 = __float2bfloat16(v.w - __bfloat162float(h3));
                hrow[i * 2 + 0] = (uint32_t)__bfloat16_as_ushort(h0) | ((uint32_t)__bfloat16_as_ushort(h1) << 16);
                hrow[i * 2 + 1] = (uint32_t)__bfloat16_as_ushort(h2) | ((uint32_t)__bfloat16_as_ushort(h3) << 16);
                lrow[i * 2 + 0] = (uint32_t)__bfloat16_as_ushort(l0) | ((uint32_t)__bfloat16_as_ushort(l1) << 16);
                lrow[i * 2 + 1] = (uint32_t)__bfloat16_as_ushort(l2) | ((uint32_t)__bfloat16_as_ushort(l3) << 16);
            }
        }
        // ---- stage B: coalesced u32 copies of transposed weights (13 x 256 = 3328) ----
        {
            const uint32_t* bhr = (const uint32_t*)d_BThi;   // [512][104] u32
            const uint32_t* blr = (const uint32_t*)d_BTlo;
            uint32_t* bsh = (uint32_t*)Bs_hi;                // [32][108] u32
            uint32_t* bsl = (uint32_t*)Bs_lo;
#pragma unroll
            for (int i = 0; i < 13; i++) {
                int idx = tid + i * 256;
                int kk = idx / 104, j = idx - kk * 104;
                bsh[kk * 108 + j] = bhr[(size_t)(k0 + kk) * 104 + j];
                bsl[kk * 108 + j] = blr[(size_t)(k0 + kk) * 104 + j];
            }
        }
        __syncthreads();
        // ---- compute: 2 k-sub x 13 n-tiles x 3 mmas ----
#pragma unroll
        for (int ksub = 0; ksub < 32; ksub += 16) {
            uint32_t ah[4], al[4];
            uint32_t aoff = ((uint32_t)((ms * 16 + (lane & 15)) * 40 + ksub + ((lane >> 4) << 3))) * 2;
            ldsm4(ah, uAh + aoff);
            ldsm4(al, uAl + aoff);
            uint32_t brow = ((uint32_t)((ksub + (lane & 15)) * 216)) * 2;
#pragma unroll
            for (int nt = 0; nt < 13; nt++) {
                uint32_t bh[2], bl[2];
                uint32_t boff = brow + (nh * 13 + nt) * 16;
                ldsm2t(bh, uBh + boff);
                ldsm2t(bl, uBl + boff);
                mma_bf16(acc[nt], ah, bh);
                mma_bf16(acc[nt], ah, bl);
                mma_bf16(acc[nt], al, bh);
            }
        }
    }

    // ---- row inverse norms (4 threads per row -> shfl reduce) ----
    sumsq += __shfl_xor_sync(0xffffffffu, sumsq, 1);
    sumsq += __shfl_xor_sync(0xffffffffu, sumsq, 2);
    if (aq == 0) sInv[ar] = rsqrtf(fmaxf(sumsq, EPS * EPS));  // == 1/max(||x||,EPS)
    __syncthreads();

    // ---- epilogue: |cos| -> NAND interp, write d_E0 ----
    const int rA = ms * 16 + (lane >> 2);
    const int mA = m0 + rA;
    const int mB = mA + 8;
    const float inxA = sInv[rA];
    const float inxB = sInv[rA + 8];
    float* eA = &d_E0[(size_t)mA * NG];
    float* eB = &d_E0[(size_t)mB * NG];
    const int c0 = nh * 104 + (lane & 3) * 2;
#pragma unroll
    for (int nt = 0; nt < 13; nt++) {
        int c = c0 + nt * 8;
        float nw0 = d_NWv[c * 3];
        float nw1 = d_NWv[(c + 1) * 3];
        float a0 = fabsf(acc[nt][0] * inxA);
        float a1 = fabsf(acc[nt][1] * inxA);
        float b0 = fabsf(acc[nt][2] * inxB);
        float b1 = fabsf(acc[nt][3] * inxB);
        eA[c]     = nw0 * a0 + (1.f - nw0) * (1.f - a0);
        eA[c + 1] = nw1 * a1 + (1.f - nw1) * (1.f - a1);
        eB[c]     = nw0 * b0 + (1.f - nw0) * (1.f - b0);
        eB[c + 1] = nw1 * b1 + (1.f - nw1) * (1.f - b1);
    }
}

// ============================================================
// Sequential scan v2.1: same structure/barriers as R15-passing, but
// fast-math intrinsics (rsqrtf / __expf / __fdividef) and split FMA chains.
// ============================================================
__global__ __launch_bounds__(512, 1) void k_scan(const float* __restrict__ sharp_in) {
    __shared__ float sM[32 * 33];                 // padded Gram (shared by lanes)
    __shared__ float sAa[2][2][2][4][32];         // [ln][buf][k][d][i]
    __shared__ float sPp[2][2][2][4];             // [ln][buf][k][d]
    __shared__ float2 sPk2[2][32];                // [ln][i] = (pk0_i, pk1_i)
    __shared__ float sNp[2][2];                   // [ln][k]  (INVERSE norms)
    __shared__ float sG[2][NG];                   // [ln][gate]
    __shared__ float sPv[2][2][32];               // [ln][k][i]
    __shared__ float sProb[2][4];                 // [ln][k*2 + {pop,push}]

    const int tid = threadIdx.x;
    const int ln  = tid >> 8;
    const int lid = tid & 255;
    const int b   = blockIdx.x * 2 + ln;
    const int barid = ln + 1;

#define LBAR() asm volatile("bar.sync %0, 256;" :: "r"(barid) : "memory")

    float rG1[32], rG2[32];
    float nw1 = 0.f, nw2 = 0.f;
    if (lid < NG) {
#pragma unroll
        for (int i = 0; i < 32; i++) {
            rG1[i] = d_Gn1[lid * 32 + i];
            rG2[i] = d_Gn2[lid * 32 + i];
        }
        nw1 = d_NWv[lid * 3 + 1];
        nw2 = d_NWv[lid * 3 + 2];
    }
    for (int idx = tid; idx < 1024; idx += 512)
        sM[(idx >> 5) * 33 + (idx & 31)] = d_M[idx];

    {
        int k = lid >> 7, d = (lid >> 5) & 3, i = lid & 31;
        sAa[ln][0][k][d][i] = (d == 1) ? ((i == 1) ? 1.f : 0.f) : ((i == 0) ? ZO : 0.f);
        if (lid < 8) sPp[ln][0][lid >> 2][lid & 3] = ((lid & 3) == 1) ? 1.f : 0.f;
    }
    const float sh0 = sharp_in[0], sh1 = sharp_in[1];
    int buf = 0;
    __syncthreads();

    // ---- initial peek + inverse norm ----
    if (lid < 64) {
        int k = lid >> 5, i = lid & 31;
        float mypk = 0.f;
#pragma unroll
        for (int d = 0; d < 4; d++) mypk += sPp[ln][buf][k][d] * sAa[ln][buf][k][d][i];
        ((float*)&sPk2[ln][i])[k] = mypk;
        float qa = 0.f, qb = 0.f;
#pragma unroll
        for (int j = 0; j < 32; j += 2) {
            qa = fmaf(sM[i * 33 + j], __shfl_sync(0xffffffffu, mypk, j), qa);
            qb = fmaf(sM[i * 33 + j + 1], __shfl_sync(0xffffffffu, mypk, j + 1), qb);
        }
        float part = mypk * (qa + qb);
        for (int o = 16; o; o >>= 1) part += __shfl_down_sync(0xffffffffu, part, o);
        if (i == 0) sNp[ln][k] = rsqrtf(fmaxf(part, EPS * EPS));
    }
    LBAR();

    float e0c = (lid < NG) ? d_E0[((size_t)0 * BB + b) * NG + lid] : 0.f;

    for (int t = 0; t < SS; t++) {
        float e0n = 0.f;
        if (lid < NG && t < SS - 1) e0n = d_E0[((size_t)(t + 1) * BB + b) * NG + lid];

        // ---- phase A gates (lid < 144), split chains ----
        if (lid < 144) {
            float inv0 = sNp[ln][0];
            float inv1 = sNp[ln][1];
            float d1a = 0.f, d1b = 0.f, d2a = 0.f, d2b = 0.f;
#pragma unroll
            for (int i = 0; i < 32; i += 2) {
                float2 pa = sPk2[ln][i];
                d1a = fmaf(pa.x, rG1[i], d1a); d2a = fmaf(pa.y, rG2[i], d2a);
                float2 pb = sPk2[ln][i + 1];
                d1b = fmaf(pb.x, rG1[i + 1], d1b); d2b = fmaf(pb.y, rG2[i + 1], d2b);
            }
            float c1 = fabsf(d1a + d1b) * inv0;
            float c2 = fabsf(d2a + d2b) * inv1;
            float t1 = nw1 * c1 + (1.f - nw1) * (1.f - c1);
            float t2 = nw2 * c2 + (1.f - nw2) * (1.f - c2);
            sG[ln][lid] = e0c * t1 * t2;
        }
        LBAR();                                   // bar1

        // ---- push coefs + push value; probs via logistic form ----
        if (lid < 64) {
            int k = lid >> 5, cc = lid & 31;
            int base = 16 + (k << 6) + (cc << 1);
            float cf = sG[ln][base] + sG[ln][base + 1];
            float cf30 = __shfl_sync(0xffffffffu, cf, 30);
            float cf31 = __shfl_sync(0xffffffffu, cf, 31);
            float cfm2 = __shfl_up_sync(0xffffffffu, cf, 2);
            float2 pk = sPk2[ln][cc];
            float v = cf30 * pk.x + cf31 * pk.y + ((cc >= 2) ? cfm2 : 0.f);
            sPv[ln][k][cc] = v;
        } else if (lid < 66) {
            int k = lid - 64;
            float sh = k ? sh1 : sh0;
            float pp = fmaxf(sG[ln][k * 4 + 0], sG[ln][k * 4 + 1]);
            float pn = fmaxf(sG[ln][k * 4 + 2], sG[ln][k * 4 + 3]);
            sProb[ln][k * 2 + 0] = __fdividef(1.f, 1.f + __expf(sh * (pn - pp)));
            float qp = fmaxf(sG[ln][8 + k * 4 + 0], sG[ln][8 + k * 4 + 1]);
            float qn = fmaxf(sG[ln][8 + k * 4 + 2], sG[ln][8 + k * 4 + 3]);
            sProb[ln][k * 2 + 1] = __fdividef(1.f, 1.f + __expf(sh * (qn - qp)));
        }
        LBAR();                                   // bar2

        // ---- stack update (double-buffered) ----
        {
            int k = lid >> 7, d = (lid >> 5) & 3, i = lid & 31;
            float a   = sAa[ln][buf][k][d][i];
            float pd  = sPp[ln][buf][k][d];
            float pdp = sPp[ln][buf][k][(d + 1) & 3];
            float pdm = sPp[ln][buf][k][(d - 1) & 3];
            float pop  = sProb[ln][k * 2 + 0];
            float push = sProb[ln][k * 2 + 1];
            float pv = sPv[ln][k][i];
            float ps = a * (1.f - pd) + ((i == 0) ? ZO : 0.f) * pd;
            float s1 = ps * pop + a * (1.f - pop);
            float prold = pd * pop + pdm * (1.f - pop);
            float p1d   = pdp * pop + pd * (1.f - pop);
            float ps2 = s1 * (1.f - prold) + pv * prold;
            float s2 = ps2 * push + s1 * (1.f - push);
            float p2 = prold * push + p1d * (1.f - push);
            sAa[ln][buf ^ 1][k][d][i] = s2;
            if (i == 0) sPp[ln][buf ^ 1][k][d] = p2;
        }
        LBAR();                                   // bar3
        buf ^= 1;

        // ---- new peeks + inverse norms ----
        if (lid < 64) {
            int k = lid >> 5, i = lid & 31;
            float mypk = 0.f;
#pragma unroll
            for (int d = 0; d < 4; d++) mypk += sPp[ln][buf][k][d] * sAa[ln][buf][k][d][i];
            ((float*)&sPk2[ln][i])[k] = mypk;
            float qa = 0.f, qb = 0.f;
#pragma unroll
            for (int j = 0; j < 32; j += 2) {
                qa = fmaf(sM[i * 33 + j], __shfl_sync(0xffffffffu, mypk, j), qa);
                qb = fmaf(sM[i * 33 + j + 1], __shfl_sync(0xffffffffu, mypk, j + 1), qb);
            }
            float part = mypk * (qa + qb);
            for (int o = 16; o; o >>= 1) part += __shfl_down_sync(0xffffffffu, part, o);
            if (i == 0) sNp[ln][k] = rsqrtf(fmaxf(part, EPS * EPS));
        }
        LBAR();                                   // bar4

        // ---- phase B: calc gates ----
        if (lid >= 144 && lid < NG) {
            float inv0 = sNp[ln][0];
            float inv1 = sNp[ln][1];
            float d1a = 0.f, d1b = 0.f, d2a = 0.f, d2b = 0.f;
#pragma unroll
            for (int i = 0; i < 32; i += 2) {
                float2 pa = sPk2[ln][i];
                d1a = fmaf(pa.x, rG1[i], d1a); d2a = fmaf(pa.y, rG2[i], d2a);
                float2 pb = sPk2[ln][i + 1];
                d1b = fmaf(pb.x, rG1[i + 1], d1b); d2b = fmaf(pb.y, rG2[i + 1], d2b);
            }
            float c1 = fabsf(d1a + d1b) * inv0;
            float c2 = fabsf(d2a + d2b) * inv1;
            float t1 = nw1 * c1 + (1.f - nw1) * (1.f - c1);
            float t2 = nw2 * c2 + (1.f - nw2) * (1.f - c2);
            sG[ln][lid] = e0c * t1 * t2;
        }
        LBAR();                                   // bar5

        // ---- output coefficients ----
        if (lid < 32) {
            int base = 144 + (lid << 1);
            float cf = sG[ln][base] + sG[ln][base + 1];
            float cf30 = __shfl_sync(0xffffffffu, cf, 30);
            float cf31 = __shfl_sync(0xffffffffu, cf, 31);
            float cfm2 = __shfl_up_sync(0xffffffffu, cf, 2);
            float2 pk = sPk2[ln][lid];
            float v = cf30 * pk.x + cf31 * pk.y + ((lid >= 2) ? cfm2 : 0.f);
            d_OC[((size_t)b * SS + t) * 32 + lid] = v;
        }
        e0c = e0n;
    }
#undef LBAR
}

// ============================================================
// Output projection
// ============================================================
__global__ __launch_bounds__(256) void k_out(const float* __restrict__ siv,
                                             const float* __restrict__ syms,
                                             float* __restrict__ out) {
    __shared__ float sv[31][256];
    __shared__ float soc[64][32];
    int v0 = blockIdx.y * 256;
    int r0 = blockIdx.x * 64;
    int tid = threadIdx.x;
#pragma unroll
    for (int e = 0; e < 31; e++) {
        int idx = tid + e * 256;
        int h = idx >> 8, v = idx & 255;
        sv[h][v] = (h == 0) ? siv[v0 + v] : syms[(h - 1) * VDIM + v0 + v];
    }
#pragma unroll
    for (int e = 0; e < 8; e++) {
        int idx = tid + e * 256;
        soc[idx >> 5][idx & 31] = d_OC[(size_t)(r0 + (idx >> 5)) * 32 + (idx & 31)];
    }
    __syncthreads();
#pragma unroll 4
    for (int rr = 0; rr < 64; rr++) {
        float acc = soc[rr][0];
        acc += soc[rr][1] * sv[0][tid];
#pragma unroll
        for (int h = 0; h < 30; h++) acc += soc[rr][2 + h] * sv[1 + h][tid];
        out[(size_t)(r0 + rr) * VDIM + v0 + tid] = acc;
    }
}

// ============================================================
extern "C" void kernel_launch(void* const* d_in, const int* in_sizes, int n_in,
                              void* d_out, int out_size) {
    const float* x         = (const float*)d_in[0];
    const float* syms      = (const float*)d_in[1];
    const float* siv       = (const float*)d_in[2];
    const float* sharp     = (const float*)d_in[3];
    const float* pop_w     = (const float*)d_in[4];
    const float* pop_nw    = (const float*)d_in[5];
    const float* pushop_w  = (const float*)d_in[6];
    const float* pushop_nw = (const float*)d_in[7];
    const float* pushfn_w  = (const float*)d_in[8];
    const float* pushfn_nw = (const float*)d_in[9];
    const float* calc_w    = (const float*)d_in[10];
    const float* calc_nw   = (const float*)d_in[11];
    float* out = (float*)d_out;

    k_gram<<<dim3(32, 32), 32>>>(siv, syms);
    k_setup<<<NG, 256>>>(siv, syms, pop_w, pop_nw, pushop_w, pushop_nw,
                         pushfn_w, pushfn_nw, calc_w, calc_nw);
    k_tr<<<dim3(16, 7), dim3(32, 8)>>>();
    k_e0<<<512, 256>>>(x);
    k_scan<<<BB / 2, 512>>>(sharp);
    k_out<<<dim3(512, 2), 256>>>(siv, syms, out);
}

// round 17
// speedup vs baseline: 2.2697x; 1.0354x over previous
#include <cuda_runtime.h>
#include <cuda_bf16.h>
#include <math.h>
#include <stdint.h>

// ---- problem constants ----
#define NG   208      // total gates: pop(8) + pushop(8) + pushfn(128) + calc(64)
#define VDIM 512
#define BB   256
#define SS   128
#define ZO   1e-6f
#define EPS  1e-8f

// ---- device scratch (no allocations allowed) ----
__device__ float d_M[32 * 32];                    // Gram of 32-dim basis
__device__ float d_Gn1[NG * 32];                  // basis . w_vec1 / max(||w_vec1||,eps)
__device__ float d_Gn2[NG * 32];                  // basis . w_vec2 / max(||w_vec2||,eps)
__device__ float d_NWv[NG * 3];                   // sigmoid(nw_raw)
__device__ __nv_bfloat16 d_Bcv_hi[(size_t)NG * VDIM]; // normalized w0 hi bf16 [c][v]
__device__ __nv_bfloat16 d_Bcv_lo[(size_t)NG * VDIM]; // residual lo bf16 [c][v]
__device__ __nv_bfloat16 d_BThi[(size_t)VDIM * NG];   // transposed [v][c]
__device__ __nv_bfloat16 d_BTlo[(size_t)VDIM * NG];   // transposed [v][c]
__device__ float d_E0[(size_t)SS * BB * NG];      // precomputed vec0 interp term
__device__ float d_OC[(size_t)BB * SS * 32];      // output coefficients

// ---- warp-MMA helpers (baseline ISA) ----
__device__ __forceinline__ uint32_t smem_u32(const void* p) {
    uint32_t a;
    asm("{ .reg .u64 t; cvta.to.shared.u64 t, %1; cvt.u32.u64 %0, t; }" : "=r"(a) : "l"(p));
    return a;
}
__device__ __forceinline__ void ldsm4(uint32_t* a, uint32_t addr) {
    asm volatile("ldmatrix.sync.aligned.m8n8.x4.shared.b16 {%0,%1,%2,%3}, [%4];"
        : "=r"(a[0]), "=r"(a[1]), "=r"(a[2]), "=r"(a[3]) : "r"(addr));
}
__device__ __forceinline__ void ldsm2t(uint32_t* b, uint32_t addr) {
    asm volatile("ldmatrix.sync.aligned.m8n8.x2.trans.shared.b16 {%0,%1}, [%2];"
        : "=r"(b[0]), "=r"(b[1]) : "r"(addr));
}
__device__ __forceinline__ void mma_bf16(float* d, const uint32_t* a, const uint32_t* b) {
    asm volatile("mma.sync.aligned.m16n8k16.row.col.f32.bf16.bf16.f32 "
        "{%0,%1,%2,%3}, {%4,%5,%6,%7}, {%8,%9}, {%0,%1,%2,%3};"
        : "+f"(d[0]), "+f"(d[1]), "+f"(d[2]), "+f"(d[3])
        : "r"(a[0]), "r"(a[1]), "r"(a[2]), "r"(a[3]), "r"(b[0]), "r"(b[1]));
}

// ============================================================
// Gram matrix of the 32-dim basis
// ============================================================
__global__ void k_gram(const float* __restrict__ siv, const float* __restrict__ syms) {
    int i = blockIdx.x, j = blockIdx.y;
    int lane = threadIdx.x;
    float s = 0.f;
    for (int v = lane; v < VDIM; v += 32) {
        float bi = (i == 0) ? 1.f : ((i == 1) ? siv[v] : syms[(i - 2) * VDIM + v]);
        float bj = (j == 0) ? 1.f : ((j == 1) ? siv[v] : syms[(j - 2) * VDIM + v]);
        s += bi * bj;
    }
    for (int o = 16; o; o >>= 1) s += __shfl_down_sync(0xffffffffu, s, o);
    if (lane == 0) d_M[i * 32 + j] = s;
}

// ============================================================
// Per-gate preprocessing (bf16 hi/lo split stored [c][v] COALESCED)
// ============================================================
__global__ void k_setup(const float* __restrict__ siv, const float* __restrict__ syms,
                        const float* __restrict__ pop_w, const float* __restrict__ pop_nw,
                        const float* __restrict__ pushop_w, const float* __restrict__ pushop_nw,
                        const float* __restrict__ pushfn_w, const float* __restrict__ pushfn_nw,
                        const float* __restrict__ calc_w, const float* __restrict__ calc_nw) {
    int c = blockIdx.x;
    const float* wb;
    const float* nb;
    if (c < 8)        { wb = pop_w    + (size_t)c * 3 * VDIM;          nb = pop_nw    + (size_t)c * 3; }
    else if (c < 16)  { wb = pushop_w + (size_t)(c - 8) * 3 * VDIM;    nb = pushop_nw + (size_t)(c - 8) * 3; }
    else if (c < 144) { wb = pushfn_w + (size_t)(c - 16) * 3 * VDIM;   nb = pushfn_nw + (size_t)(c - 16) * 3; }
    else              { wb = calc_w   + (size_t)(c - 144) * 3 * VDIM;  nb = calc_nw   + (size_t)(c - 144) * 3; }

    __shared__ float sg[67];
    int warp = threadIdx.x >> 5, lane = threadIdx.x & 31;
    for (int job = warp; job < 67; job += 8) {
        const float* w;
        int bi;
        if (job < 64) { bi = job >> 1; w = wb + ((job & 1) + 1) * VDIM; }
        else          { bi = -1;       w = wb + (job - 64) * VDIM; }
        float s = 0.f;
        for (int v = lane; v < VDIM; v += 32) {
            float wv = w[v];
            float bv = (bi < 0) ? wv
                     : ((bi == 0) ? 1.f : ((bi == 1) ? siv[v] : syms[(bi - 2) * VDIM + v]));
            s += wv * bv;
        }
        for (int o = 16; o; o >>= 1) s += __shfl_down_sync(0xffffffffu, s, o);
        if (!lane) sg[job] = s;
    }
    __syncthreads();
    if (threadIdx.x < 64) {
        int bi = threadIdx.x >> 1, vecsel = threadIdx.x & 1;
        float n = fmaxf(sqrtf(sg[65 + vecsel]), EPS);
        float g = sg[threadIdx.x] / n;
        if (vecsel == 0) d_Gn1[c * 32 + bi] = g;
        else             d_Gn2[c * 32 + bi] = g;
    }
    if (threadIdx.x < 3) d_NWv[c * 3 + threadIdx.x] = 1.f / (1.f + expf(-nb[threadIdx.x]));
    float n0 = fmaxf(sqrtf(sg[64]), EPS);
    for (int v = threadIdx.x; v < VDIM; v += blockDim.x) {
        float val = wb[v] / n0;
        __nv_bfloat16 h = __float2bfloat16(val);
        d_Bcv_hi[(size_t)c * VDIM + v] = h;
        d_Bcv_lo[(size_t)c * VDIM + v] = __float2bfloat16(val - __bfloat162float(h));
    }
}

// ============================================================
// Tiled transpose [c][v] -> [v][c] for both hi and lo
// ============================================================
__global__ void k_tr() {
    __shared__ __nv_bfloat16 th[32][33], tl[32][33];
    int v0 = blockIdx.x * 32, c0 = blockIdx.y * 32;
    int tx = threadIdx.x, ty = threadIdx.y;
#pragma unroll
    for (int r = 0; r < 4; r++) {
        int c = c0 + ty + r * 8;
        if (c < NG) {
            th[ty + r * 8][tx] = d_Bcv_hi[(size_t)c * VDIM + v0 + tx];
            tl[ty + r * 8][tx] = d_Bcv_lo[(size_t)c * VDIM + v0 + tx];
        }
    }
    __syncthreads();
#pragma unroll
    for (int r = 0; r < 4; r++) {
        int v = v0 + ty + r * 8;
        int c = c0 + tx;
        if (c < NG) {
            d_BThi[(size_t)v * NG + c] = th[tx][ty + r * 8];
            d_BTlo[(size_t)v * NG + c] = tl[tx][ty + r * 8];
        }
    }
}

// ============================================================
// E0 GEMM v3 (unchanged R16-passing): mma.sync bf16 hi/lo split, 2 CTAs/SM.
// ============================================================
__global__ __launch_bounds__(256, 2) void k_e0(const float* __restrict__ x) {
    __shared__ __align__(16) __nv_bfloat16 As_hi[64 * 40];
    __shared__ __align__(16) __nv_bfloat16 As_lo[64 * 40];
    __shared__ __align__(16) __nv_bfloat16 Bs_hi[32 * 216];
    __shared__ __align__(16) __nv_bfloat16 Bs_lo[32 * 216];
    __shared__ float sInv[64];

    const int tid = threadIdx.x;
    const int wid = tid >> 5, lane = tid & 31;
    const int ms = wid & 3, nh = wid >> 2;
    const int m0 = blockIdx.x * 64;

    const uint32_t uAh = smem_u32(As_hi), uAl = smem_u32(As_lo);
    const uint32_t uBh = smem_u32(Bs_hi), uBl = smem_u32(Bs_lo);

    float acc[13][4];
#pragma unroll
    for (int nt = 0; nt < 13; nt++)
#pragma unroll
        for (int q = 0; q < 4; q++) acc[nt][q] = 0.f;

    const int ar = tid >> 2, aq = tid & 3;
    const int am = m0 + ar;
    const float* xrow = x + ((size_t)((am & 255) * SS + (am >> 8))) * VDIM + aq * 8;
    float sumsq = 0.f;

    for (int ch = 0; ch < 16; ch++) {
        const int k0 = ch * 32;
        __syncthreads();
        {
            uint32_t* hrow = (uint32_t*)(As_hi + ar * 40 + aq * 8);
            uint32_t* lrow = (uint32_t*)(As_lo + ar * 40 + aq * 8);
#pragma unroll
            for (int i = 0; i < 2; i++) {
                float4 v = *(const float4*)(xrow + k0 + i * 4);
                sumsq += v.x * v.x + v.y * v.y + v.z * v.z + v.w * v.w;
                __nv_bfloat16 h0 = __float2bfloat16(v.x);
                __nv_bfloat16 h1 = __float2bfloat16(v.y);
                __nv_bfloat16 h2 = __float2bfloat16(v.z);
                __nv_bfloat16 h3 = __float2bfloat16(v.w);
                __nv_bfloat16 l0 = __float2bfloat16(v.x - __bfloat162float(h0));
                __nv_bfloat16 l1 = __float2bfloat16(v.y - __bfloat162float(h1));
                __nv_bfloat16 l2 = __float2bfloat16(v.z - __bfloat162float(h2));
                __nv_bfloat16 l3 = __float2bfloat16(v.w - __bfloat162float(h3));
                hrow[i * 2 + 0] = (uint32_t)__bfloat16_as_ushort(h0) | ((uint32_t)__bfloat16_as_ushort(h1) << 16);
                hrow[i * 2 + 1] = (uint32_t)__bfloat16_as_ushort(h2) | ((uint32_t)__bfloat16_as_ushort(h3) << 16);
                lrow[i * 2 + 0] = (uint32_t)__bfloat16_as_ushort(l0) | ((uint32_t)__bfloat16_as_ushort(l1) << 16);
                lrow[i * 2 + 1] = (uint32_t)__bfloat16_as_ushort(l2) | ((uint32_t)__bfloat16_as_ushort(l3) << 16);
            }
        }
        {
            const uint32_t* bhr = (const uint32_t*)d_BThi;   // [512][104] u32
            const uint32_t* blr = (const uint32_t*)d_BTlo;
            uint32_t* bsh = (uint32_t*)Bs_hi;                // [32][108] u32
            uint32_t* bsl = (uint32_t*)Bs_lo;
#pragma unroll
            for (int i = 0; i < 13; i++) {
                int idx = tid + i * 256;
                int kk = idx / 104, j = idx - kk * 104;
                bsh[kk * 108 + j] = bhr[(size_t)(k0 + kk) * 104 + j];
                bsl[kk * 108 + j] = blr[(size_t)(k0 + kk) * 104 + j];
            }
        }
        __syncthreads();
#pragma unroll
        for (int ksub = 0; ksub < 32; ksub += 16) {
            uint32_t ah[4], al[4];
            uint32_t aoff = ((uint32_t)((ms * 16 + (lane & 15)) * 40 + ksub + ((lane >> 4) << 3))) * 2;
            ldsm4(ah, uAh + aoff);
            ldsm4(al, uAl + aoff);
            uint32_t brow = ((uint32_t)((ksub + (lane & 15)) * 216)) * 2;
#pragma unroll
            for (int nt = 0; nt < 13; nt++) {
                uint32_t bh[2], bl[2];
                uint32_t boff = brow + (nh * 13 + nt) * 16;
                ldsm2t(bh, uBh + boff);
                ldsm2t(bl, uBl + boff);
                mma_bf16(acc[nt], ah, bh);
                mma_bf16(acc[nt], ah, bl);
                mma_bf16(acc[nt], al, bh);
            }
        }
    }

    sumsq += __shfl_xor_sync(0xffffffffu, sumsq, 1);
    sumsq += __shfl_xor_sync(0xffffffffu, sumsq, 2);
    if (aq == 0) sInv[ar] = rsqrtf(fmaxf(sumsq, EPS * EPS));
    __syncthreads();

    const int rA = ms * 16 + (lane >> 2);
    const int mA = m0 + rA;
    const int mB = mA + 8;
    const float inxA = sInv[rA];
    const float inxB = sInv[rA + 8];
    float* eA = &d_E0[(size_t)mA * NG];
    float* eB = &d_E0[(size_t)mB * NG];
    const int c0 = nh * 104 + (lane & 3) * 2;
#pragma unroll
    for (int nt = 0; nt < 13; nt++) {
        int c = c0 + nt * 8;
        float nw0 = d_NWv[c * 3];
        float nw1 = d_NWv[(c + 1) * 3];
        float a0 = fabsf(acc[nt][0] * inxA);
        float a1 = fabsf(acc[nt][1] * inxA);
        float b0 = fabsf(acc[nt][2] * inxB);
        float b1 = fabsf(acc[nt][3] * inxB);
        eA[c]     = nw0 * a0 + (1.f - nw0) * (1.f - a0);
        eA[c + 1] = nw1 * a1 + (1.f - nw1) * (1.f - a1);
        eB[c]     = nw0 * b0 + (1.f - nw0) * (1.f - b0);
        eB[c + 1] = nw1 * b1 + (1.f - nw1) * (1.f - b1);
    }
}

// ============================================================
// Sequential scan v3: 4 named barriers/step.
//  - probs + push-values computed INLINE by stack-update threads
//    (broadcast LDS + 2 __expf each) — pv/prob phase & barrier removed
//  - out-coef(t-1) runs in warp 7 concurrently with phase A of step t
//  - interp identity: nw*c+(1-nw)(1-c) = (2nw-1)*c + (1-nw)
// ============================================================
__global__ __launch_bounds__(512, 1) void k_scan(const float* __restrict__ sharp_in) {
    __shared__ float sM[32 * 33];                 // padded Gram (shared by lanes)
    __shared__ float sAa[2][2][2][4][32];         // [ln][buf][k][d][i]
    __shared__ float sPp[2][2][2][4];             // [ln][buf][k][d]
    __shared__ float2 sPk2[2][32];                // [ln][i] = (pk0_i, pk1_i)
    __shared__ float sNp[2][2];                   // [ln][k]  (INVERSE norms)
    __shared__ float sG[2][NG];                   // [ln][gate]

    const int tid = threadIdx.x;
    const int ln  = tid >> 8;
    const int lid = tid & 255;
    const int b   = blockIdx.x * 2 + ln;
    const int barid = ln + 1;

#define LBAR() asm volatile("bar.sync %0, 256;" :: "r"(barid) : "memory")

    float rG1[32], rG2[32];
    float ia1 = 0.f, ib1 = 0.f, ia2 = 0.f, ib2 = 0.f;
    if (lid < NG) {
#pragma unroll
        for (int i = 0; i < 32; i++) {
            rG1[i] = d_Gn1[lid * 32 + i];
            rG2[i] = d_Gn2[lid * 32 + i];
        }
        float nw1 = d_NWv[lid * 3 + 1];
        float nw2 = d_NWv[lid * 3 + 2];
        ia1 = 2.f * nw1 - 1.f; ib1 = 1.f - nw1;
        ia2 = 2.f * nw2 - 1.f; ib2 = 1.f - nw2;
    }
    for (int idx = tid; idx < 1024; idx += 512)
        sM[(idx >> 5) * 33 + (idx & 31)] = d_M[idx];

    {
        int k = lid >> 7, d = (lid >> 5) & 3, i = lid & 31;
        sAa[ln][0][k][d][i] = (d == 1) ? ((i == 1) ? 1.f : 0.f) : ((i == 0) ? ZO : 0.f);
        if (lid < 8) sPp[ln][0][lid >> 2][lid & 3] = ((lid & 3) == 1) ? 1.f : 0.f;
    }
    const float sh0 = sharp_in[0], sh1 = sharp_in[1];
    int buf = 0;
    __syncthreads();

    // ---- initial peek + inverse norm ----
    if (lid < 64) {
        int k = lid >> 5, i = lid & 31;
        float mypk = 0.f;
#pragma unroll
        for (int d = 0; d < 4; d++) mypk += sPp[ln][buf][k][d] * sAa[ln][buf][k][d][i];
        ((float*)&sPk2[ln][i])[k] = mypk;
        float qa = 0.f, qb = 0.f;
#pragma unroll
        for (int j = 0; j < 32; j += 2) {
            qa = fmaf(sM[i * 33 + j], __shfl_sync(0xffffffffu, mypk, j), qa);
            qb = fmaf(sM[i * 33 + j + 1], __shfl_sync(0xffffffffu, mypk, j + 1), qb);
        }
        float part = mypk * (qa + qb);
        for (int o = 16; o; o >>= 1) part += __shfl_down_sync(0xffffffffu, part, o);
        if (i == 0) sNp[ln][k] = rsqrtf(fmaxf(part, EPS * EPS));
    }
    LBAR();

    float e0c = (lid < NG) ? d_E0[((size_t)0 * BB + b) * NG + lid] : 0.f;

    for (int t = 0; t < SS; t++) {
        float e0n = 0.f;
        if (lid < NG && t < SS - 1) e0n = d_E0[((size_t)(t + 1) * BB + b) * NG + lid];

        // ---- slot 1: phase A gates (lid<144) || out-coef(t-1) (warp 7) ----
        if (lid < 144) {
            float inv0 = sNp[ln][0];
            float inv1 = sNp[ln][1];
            float d1a = 0.f, d1b = 0.f, d2a = 0.f, d2b = 0.f;
#pragma unroll
            for (int i = 0; i < 32; i += 2) {
                float2 pa = sPk2[ln][i];
                d1a = fmaf(pa.x, rG1[i], d1a); d2a = fmaf(pa.y, rG2[i], d2a);
                float2 pb = sPk2[ln][i + 1];
                d1b = fmaf(pb.x, rG1[i + 1], d1b); d2b = fmaf(pb.y, rG2[i + 1], d2b);
            }
            float c1 = fabsf(d1a + d1b) * inv0;
            float c2 = fabsf(d2a + d2b) * inv1;
            float t1 = fmaf(ia1, c1, ib1);
            float t2 = fmaf(ia2, c2, ib2);
            sG[ln][lid] = e0c * t1 * t2;
        } else if (lid >= 224 && t > 0) {
            int j = lid - 224;
            float cf   = sG[ln][144 + 2 * j] + sG[ln][145 + 2 * j];
            float cf30 = sG[ln][204] + sG[ln][205];
            float cf31 = sG[ln][206] + sG[ln][207];
            float cfm2 = (j >= 2) ? (sG[ln][140 + 2 * j] + sG[ln][141 + 2 * j]) : 0.f;
            (void)cf;
            float2 pk = sPk2[ln][j];
            float v = cf30 * pk.x + cf31 * pk.y + cfm2;
            d_OC[((size_t)b * SS + (t - 1)) * 32 + j] = v;
        }
        LBAR();                                   // bar A: sG[0..143] ready

        // ---- slot 2: stack update, probs + pv inline (all 256 threads) ----
        {
            int k = lid >> 7, d = (lid >> 5) & 3, i = lid & 31;
            float sh = k ? sh1 : sh0;
            float pp = fmaxf(sG[ln][k * 4 + 0], sG[ln][k * 4 + 1]);
            float pn = fmaxf(sG[ln][k * 4 + 2], sG[ln][k * 4 + 3]);
            float pop = __fdividef(1.f, 1.f + __expf(sh * (pn - pp)));
            float qp = fmaxf(sG[ln][8 + k * 4 + 0], sG[ln][8 + k * 4 + 1]);
            float qn = fmaxf(sG[ln][8 + k * 4 + 2], sG[ln][8 + k * 4 + 3]);
            float push = __fdividef(1.f, 1.f + __expf(sh * (qn - qp)));
            int gb = 16 + (k << 6);
            float cf30 = sG[ln][gb + 60] + sG[ln][gb + 61];
            float cf31 = sG[ln][gb + 62] + sG[ln][gb + 63];
            float cfi  = (i >= 2) ? (sG[ln][gb + 2 * i - 4] + sG[ln][gb + 2 * i - 3]) : 0.f;
            float2 pk = sPk2[ln][i];
            float pv = cf30 * pk.x + cf31 * pk.y + cfi;

            float a   = sAa[ln][buf][k][d][i];
            float pd  = sPp[ln][buf][k][d];
            float pdp = sPp[ln][buf][k][(d + 1) & 3];
            float pdm = sPp[ln][buf][k][(d - 1) & 3];
            float ps = a * (1.f - pd) + ((i == 0) ? ZO : 0.f) * pd;
            float s1 = ps * pop + a * (1.f - pop);
            float prold = pd * pop + pdm * (1.f - pop);   // roll(p_after_pop,+1)[d]
            float p1d   = pdp * pop + pd * (1.f - pop);   // p_after_pop[d]
            float ps2 = s1 * (1.f - prold) + pv * prold;
            float s2 = ps2 * push + s1 * (1.f - push);
            float p2 = prold * push + p1d * (1.f - push);
            sAa[ln][buf ^ 1][k][d][i] = s2;
            if (i == 0) sPp[ln][buf ^ 1][k][d] = p2;
        }
        LBAR();                                   // bar B: new stacks ready
        buf ^= 1;

        // ---- slot 3: new peeks + inverse norms (lid<64) ----
        if (lid < 64) {
            int k = lid >> 5, i = lid & 31;
            float mypk = 0.f;
#pragma unroll
            for (int d = 0; d < 4; d++) mypk += sPp[ln][buf][k][d] * sAa[ln][buf][k][d][i];
            ((float*)&sPk2[ln][i])[k] = mypk;
            float qa = 0.f, qb = 0.f;
#pragma unroll
            for (int j = 0; j < 32; j += 2) {
                qa = fmaf(sM[i * 33 + j], __shfl_sync(0xffffffffu, mypk, j), qa);
                qb = fmaf(sM[i * 33 + j + 1], __shfl_sync(0xffffffffu, mypk, j + 1), qb);
            }
            float part = mypk * (qa + qb);
            for (int o = 16; o; o >>= 1) part += __shfl_down_sync(0xffffffffu, part, o);
            if (i == 0) sNp[ln][k] = rsqrtf(fmaxf(part, EPS * EPS));
        }
        LBAR();                                   // bar C: sPk2 + sNp ready

        // ---- slot 4: phase B calc gates (lid 144..207) ----
        if (lid >= 144 && lid < NG) {
            float inv0 = sNp[ln][0];
            float inv1 = sNp[ln][1];
            float d1a = 0.f, d1b = 0.f, d2a = 0.f, d2b = 0.f;
#pragma unroll
            for (int i = 0; i < 32; i += 2) {
                float2 pa = sPk2[ln][i];
                d1a = fmaf(pa.x, rG1[i], d1a); d2a = fmaf(pa.y, rG2[i], d2a);
                float2 pb = sPk2[ln][i + 1];
                d1b = fmaf(pb.x, rG1[i + 1], d1b); d2b = fmaf(pb.y, rG2[i + 1], d2b);
            }
            float c1 = fabsf(d1a + d1b) * inv0;
            float c2 = fabsf(d2a + d2b) * inv1;
            float t1 = fmaf(ia1, c1, ib1);
            float t2 = fmaf(ia2, c2, ib2);
            sG[ln][lid] = e0c * t1 * t2;
        }
        LBAR();                                   // bar D: sG[144..207] ready

        e0c = e0n;
    }

    // ---- final out-coef for t = SS-1 ----
    if (lid >= 224) {
        int j = lid - 224;
        float cf30 = sG[ln][204] + sG[ln][205];
        float cf31 = sG[ln][206] + sG[ln][207];
        float cfm2 = (j >= 2) ? (sG[ln][140 + 2 * j] + sG[ln][141 + 2 * j]) : 0.f;
        float2 pk = sPk2[ln][j];
        float v = cf30 * pk.x + cf31 * pk.y + cfm2;
        d_OC[((size_t)b * SS + (SS - 1)) * 32 + j] = v;
    }
#undef LBAR
}

// ============================================================
// Output projection
// ============================================================
__global__ __launch_bounds__(256) void k_out(const float* __restrict__ siv,
                                             const float* __restrict__ syms,
                                             float* __restrict__ out) {
    __shared__ float sv[31][256];
    __shared__ float soc[64][32];
    int v0 = blockIdx.y * 256;
    int r0 = blockIdx.x * 64;
    int tid = threadIdx.x;
#pragma unroll
    for (int e = 0; e < 31; e++) {
        int idx = tid + e * 256;
        int h = idx >> 8, v = idx & 255;
        sv[h][v] = (h == 0) ? siv[v0 + v] : syms[(h - 1) * VDIM + v0 + v];
    }
#pragma unroll
    for (int e = 0; e < 8; e++) {
        int idx = tid + e * 256;
        soc[idx >> 5][idx & 31] = d_OC[(size_t)(r0 + (idx >> 5)) * 32 + (idx & 31)];
    }
    __syncthreads();
#pragma unroll 4
    for (int rr = 0; rr < 64; rr++) {
        float acc = soc[rr][0];
        acc += soc[rr][1] * sv[0][tid];
#pragma unroll
        for (int h = 0; h < 30; h++) acc += soc[rr][2 + h] * sv[1 + h][tid];
        out[(size_t)(r0 + rr) * VDIM + v0 + tid] = acc;
    }
}

// ============================================================
extern "C" void kernel_launch(void* const* d_in, const int* in_sizes, int n_in,
                              void* d_out, int out_size) {
    const float* x         = (const float*)d_in[0];
    const float* syms      = (const float*)d_in[1];
    const float* siv       = (const float*)d_in[2];
    const float* sharp     = (const float*)d_in[3];
    const float* pop_w     = (const float*)d_in[4];
    const float* pop_nw    = (const float*)d_in[5];
    const float* pushop_w  = (const float*)d_in[6];
    const float* pushop_nw = (const float*)d_in[7];
    const float* pushfn_w  = (const float*)d_in[8];
    const float* pushfn_nw = (const float*)d_in[9];
    const float* calc_w    = (const float*)d_in[10];
    const float* calc_nw   = (const float*)d_in[11];
    float* out = (float*)d_out;

    k_gram<<<dim3(32, 32), 32>>>(siv, syms);
    k_setup<<<NG, 256>>>(siv, syms, pop_w, pop_nw, pushop_w, pushop_nw,
                         pushfn_w, pushfn_nw, calc_w, calc_nw);
    k_tr<<<dim3(16, 7), dim3(32, 8)>>>();
    k_e0<<<512, 256>>>(x);
    k_scan<<<BB / 2, 512>>>(sharp);
    k_out<<<dim3(512, 2), 256>>>(siv, syms, out);
}